// round 15
// baseline (speedup 1.0000x reference)
#include <cuda_runtime.h>
#include <cstdint>

#define BB 2
#define SS 4096
#define DD 1024
#define HH 8
#define DKk 128
#define DVv 128
#define SEGL 512
#define NSEG 8
#define BH (BB*HH)
#define MATS (BH*NSEG)   // 128

#define SCALE 0.08838834764831845f  // 1/sqrt(128)

// -------------------- scratch --------------------
__device__ float g_q[(size_t)BB*SS*HH*DKk];   // tf32-rounded at proj epilogue
__device__ float g_k[(size_t)BB*SS*HH*DKk];   // tf32-rounded at proj epilogue
__device__ float g_v[(size_t)BB*SS*HH*DVv];   // tf32-rounded at proj epilogue
__device__ float g_att[(size_t)BB*SS*HH*DVv];
__device__ float g_skT[(size_t)MATS*DKk*SEGL];
__device__ float g_P1[(size_t)MATS*DKk*DVv];
__device__ float g_D [(size_t)MATS*DKk*DVv];
__device__ float g_mems[(size_t)MATS*DKk*DVv];
__device__ float g_zall[MATS*DKk];
__device__ float g_zsp[MATS*8*DKk];
__device__ float g_dnv[MATS*SEGL];

// -------------------- tf32 helpers --------------------
__device__ __forceinline__ uint32_t f2tf(float f) {
    uint32_t u; asm("cvt.rna.tf32.f32 %0, %1;" : "=r"(u) : "f"(f)); return u;
}
__device__ __forceinline__ float ftf(float f) { return __uint_as_float(f2tf(f)); }
__device__ __forceinline__ float4 cvt4tf(float4 v) {
    float4 r;
    r.x = ftf(v.x); r.y = ftf(v.y); r.z = ftf(v.z); r.w = ftf(v.w);
    return r;
}
__device__ __forceinline__ void mma8(float* c, uint32_t a0, uint32_t a1, uint32_t a2, uint32_t a3,
                                     uint32_t b0, uint32_t b1) {
    asm volatile("mma.sync.aligned.m16n8k8.row.col.f32.tf32.tf32.f32 "
                 "{%0,%1,%2,%3}, {%4,%5,%6,%7}, {%8,%9}, {%0,%1,%2,%3};"
                 : "+f"(c[0]), "+f"(c[1]), "+f"(c[2]), "+f"(c[3])
                 : "r"(a0), "r"(a1), "r"(a2), "r"(a3), "r"(b0), "r"(b1));
}
__device__ __forceinline__ float elu1(float x) { return (x > 0.0f) ? x + 1.0f : __expf(x); }

// -------------------- generic 128x128 CTA tf32 GEMM body (2-stage pipeline) --------------------
// RC: round C to tf32 (RNA) at the epilogue write.
template<int K, bool RC>
__device__ __forceinline__ void gemm_body(const float* __restrict__ A, int lda,
                                          const float* __restrict__ Bb, int ldb,
                                          float* __restrict__ C, int ldc,
                                          int n0, int m0) {
    __shared__ float As[2][128 * 20];
    __shared__ float Bs[2][16 * 136];

    int t = threadIdx.x;
    int ar = t >> 2, ac = (t & 3) * 4;
    int br = t >> 5, bc = (t & 31) * 4;
    int warp = t >> 5, lane = t & 31;
    int wm = warp >> 2, wn = warp & 3;
    int gid = lane >> 2, tq = lane & 3;

    const float* Ap0 = A + (size_t)(m0 + ar) * lda + ac;
    const float* Ap1 = Ap0 + (size_t)64 * lda;
    const float* Bp0 = Bb + (size_t)br * ldb + bc;
    const float* Bp1 = Bp0 + (size_t)8 * ldb;

    float4 a0r = *(const float4*)Ap0;
    float4 a1r = *(const float4*)Ap1;
    float4 b0r = *(const float4*)Bp0;
    float4 b1r = *(const float4*)Bp1;

    *(float4*)(As[0] + ar * 20 + ac)        = cvt4tf(a0r);
    *(float4*)(As[0] + (ar + 64) * 20 + ac) = cvt4tf(a1r);
    *(float4*)(Bs[0] + br * 136 + bc)       = cvt4tf(b0r);
    *(float4*)(Bs[0] + (br + 8) * 136 + bc) = cvt4tf(b1r);
    __syncthreads();

    float acc[4][4][4];
#pragma unroll
    for (int i = 0; i < 4; i++)
#pragma unroll
        for (int j = 0; j < 4; j++)
#pragma unroll
            for (int q = 0; q < 4; q++) acc[i][j][q] = 0.0f;

    int cur = 0;
    for (int k0 = 0; k0 < K; k0 += 16) {
        bool more = (k0 + 16 < K);
        if (more) {
            Ap0 += 16; Ap1 += 16;
            Bp0 += (size_t)16 * ldb; Bp1 += (size_t)16 * ldb;
            a0r = *(const float4*)Ap0; a1r = *(const float4*)Ap1;
            b0r = *(const float4*)Bp0; b1r = *(const float4*)Bp1;
        }

        const uint32_t* Asu = (const uint32_t*)As[cur];
        const uint32_t* Bsu = (const uint32_t*)Bs[cur];
#pragma unroll
        for (int kb = 0; kb < 16; kb += 8) {
            uint32_t af[4][4], bf[4][2];
#pragma unroll
            for (int tm = 0; tm < 4; tm++) {
                int mb = wm * 64 + tm * 16;
                af[tm][0] = Asu[(mb + gid) * 20 + kb + tq];
                af[tm][1] = Asu[(mb + gid + 8) * 20 + kb + tq];
                af[tm][2] = Asu[(mb + gid) * 20 + kb + tq + 4];
                af[tm][3] = Asu[(mb + gid + 8) * 20 + kb + tq + 4];
            }
#pragma unroll
            for (int tn = 0; tn < 4; tn++) {
                int nb = wn * 32 + tn * 8 + gid;
                bf[tn][0] = Bsu[(kb + tq) * 136 + nb];
                bf[tn][1] = Bsu[(kb + tq + 4) * 136 + nb];
            }
#pragma unroll
            for (int tm = 0; tm < 4; tm++)
#pragma unroll
                for (int tn = 0; tn < 4; tn++)
                    mma8(acc[tm][tn], af[tm][0], af[tm][1], af[tm][2], af[tm][3],
                         bf[tn][0], bf[tn][1]);
        }

        if (more) {
            int nxt = cur ^ 1;
            *(float4*)(As[nxt] + ar * 20 + ac)        = cvt4tf(a0r);
            *(float4*)(As[nxt] + (ar + 64) * 20 + ac) = cvt4tf(a1r);
            *(float4*)(Bs[nxt] + br * 136 + bc)       = cvt4tf(b0r);
            *(float4*)(Bs[nxt] + (br + 8) * 136 + bc) = cvt4tf(b1r);
        }
        __syncthreads();
        cur ^= 1;
    }

#pragma unroll
    for (int tm = 0; tm < 4; tm++) {
        int row = m0 + wm * 64 + tm * 16 + gid;
#pragma unroll
        for (int tn = 0; tn < 4; tn++) {
            int col = n0 + wn * 32 + tn * 8 + 2 * tq;
            float c0 = RC ? ftf(acc[tm][tn][0]) : acc[tm][tn][0];
            float c1 = RC ? ftf(acc[tm][tn][1]) : acc[tm][tn][1];
            float c2 = RC ? ftf(acc[tm][tn][2]) : acc[tm][tn][2];
            float c3 = RC ? ftf(acc[tm][tn][3]) : acc[tm][tn][3];
            *(float2*)&C[(size_t)row * ldc + col] = make_float2(c0, c1);
            *(float2*)&C[(size_t)(row + 8) * ldc + col] = make_float2(c2, c3);
        }
    }
}

__global__ __launch_bounds__(256) void proj_mma(const float* __restrict__ x,
                                                const float* __restrict__ Wq,
                                                const float* __restrict__ Wk,
                                                const float* __restrict__ Wv) {
    const float* W = (blockIdx.z == 0) ? Wq : (blockIdx.z == 1) ? Wk : Wv;
    float* C = (blockIdx.z == 0) ? g_q : (blockIdx.z == 1) ? g_k : g_v;
    gemm_body<1024, true>(x, 1024, W + (size_t)blockIdx.y * 131072, 128,
                          C, 1024, blockIdx.y * 128, blockIdx.x * 128);
}

__global__ __launch_bounds__(256) void out_mma(const float* __restrict__ Wout,
                                               float* __restrict__ C) {
    gemm_body<1024, false>(g_att, 1024, Wout + (size_t)blockIdx.y * 128, 1024,
                           C, 1024, blockIdx.y * 128, blockIdx.x * 128);
}

// -------------------- K1: sigma_k + transpose + z partials --------------------
__global__ __launch_bounds__(256) void sig_kernel() {
    __shared__ float sm[64 * 132];
    int bh = blockIdx.x, seg = blockIdx.y, stile = blockIdx.z;
    int b = bh >> 3, h = bh & 7;
    int mat = bh * NSEG + seg;
    int s0 = stile * 64;
    int t = threadIdx.x;

    const float* kbase = g_k + ((size_t)b * SS + seg * SEGL + s0) * 1024 + h * 128;
#pragma unroll
    for (int p = 0; p < 32; p++) {
        int lin = t + p * 256;
        int row = lin >> 7, col = lin & 127;
        sm[row * 132 + col] = elu1(kbase[(size_t)row * 1024 + col]);
    }
    __syncthreads();

    float* skT = g_skT + (size_t)mat * DKk * SEGL;
#pragma unroll
    for (int p = 0; p < 32; p++) {
        int lin = t + p * 256;
        int kc = lin >> 6, scol = lin & 63;
        skT[(size_t)kc * SEGL + s0 + scol] = sm[scol * 132 + kc];
    }
    if (t < 128) {
        float zs = 0.0f;
#pragma unroll 8
        for (int s = 0; s < 64; s++) zs += sm[s * 132 + t];
        g_zsp[(mat * 8 + stile) * DKk + t] = zs;
    }
}

// -------------------- K2: z prefix --------------------
__global__ void zprefix_kernel() {
    int bh = blockIdx.x, t = threadIdx.x;  // block 128
    float z = 1.0f / (float)DKk;
    for (int s = 0; s < NSEG; s++) {
        int mat = bh * NSEG + s;
        g_zall[mat * DKk + t] = z;
#pragma unroll
        for (int st = 0; st < 8; st++) z += g_zsp[(mat * 8 + st) * DKk + t];
    }
}

// -------------------- K3: per-token 1/dn (grid split x4) --------------------
__global__ __launch_bounds__(128) void dn_kernel() {
    __shared__ float zs[128];
    int mat = blockIdx.x;
    int s0 = blockIdx.y * 128;
    int bh = mat >> 3, seg = mat & 7;
    int b = bh >> 3, h = bh & 7;
    int t = threadIdx.x;
    zs[t] = g_zall[mat * DKk + t];
    __syncthreads();
    const float* kr = g_k + ((size_t)b * SS + seg * SEGL + s0 + t) * 1024 + h * 128;
    float d = 0.0f;
#pragma unroll 8
    for (int i = 0; i < 32; i++) {
        float4 v = *(const float4*)(kr + i * 4);
        d += elu1(v.x) * zs[i * 4 + 0];
        d += elu1(v.y) * zs[i * 4 + 1];
        d += elu1(v.z) * zs[i * 4 + 2];
        d += elu1(v.w) * zs[i * 4 + 3];
    }
    g_dnv[mat * SEGL + s0 + t] = 1.0f / d;
}

// -------------------- K4: P1 and D GEMMs --------------------
__global__ __launch_bounds__(256) void pd_kernel() {
    __shared__ float As[2][128 * 20];
    __shared__ float Bs[2][16 * 136];

    int mat = blockIdx.x;
    bool isD = (blockIdx.y == 1);
    int bh = mat >> 3, seg = mat & 7;
    int b = bh >> 3, h = bh & 7;

    const float* A = g_skT + (size_t)mat * DKk * SEGL;
    const float* Bb = (isD ? g_k : g_v) + ((size_t)b * SS + seg * SEGL) * 1024 + h * 128;
    float* C = (isD ? g_D : g_P1) + (size_t)mat * DKk * DVv;
    const float* invp = g_dnv + mat * SEGL;

    int t = threadIdx.x;
    int ar = t >> 2, ac = (t & 3) * 4;
    int br = t >> 5, bc = (t & 31) * 4;
    int warp = t >> 5, lane = t & 31;
    int wm = warp >> 2, wn = warp & 3;
    int gid = lane >> 2, tq = lane & 3;

    const float* Ap0 = A + (size_t)ar * SEGL + ac;
    const float* Ap1 = Ap0 + (size_t)64 * SEGL;
    const float* Bp0 = Bb + (size_t)br * 1024 + bc;
    const float* Bp1 = Bp0 + (size_t)8 * 1024;

    float4 a0r = *(const float4*)Ap0;
    float4 a1r = *(const float4*)Ap1;
    float4 b0r = *(const float4*)Bp0;
    float4 b1r = *(const float4*)Bp1;
    float iv0 = isD ? invp[br] : 1.0f;
    float iv1 = isD ? invp[8 + br] : 1.0f;

    float4 tb0 = b0r, tb1 = b1r;
    if (isD) {
        tb0 = make_float4(elu1(b0r.x) * iv0, elu1(b0r.y) * iv0, elu1(b0r.z) * iv0, elu1(b0r.w) * iv0);
        tb1 = make_float4(elu1(b1r.x) * iv1, elu1(b1r.y) * iv1, elu1(b1r.z) * iv1, elu1(b1r.w) * iv1);
    }
    *(float4*)(As[0] + ar * 20 + ac)        = cvt4tf(a0r);
    *(float4*)(As[0] + (ar + 64) * 20 + ac) = cvt4tf(a1r);
    *(float4*)(Bs[0] + br * 136 + bc)       = cvt4tf(tb0);
    *(float4*)(Bs[0] + (br + 8) * 136 + bc) = cvt4tf(tb1);
    __syncthreads();

    float acc[4][4][4];
#pragma unroll
    for (int i = 0; i < 4; i++)
#pragma unroll
        for (int j = 0; j < 4; j++)
#pragma unroll
            for (int q = 0; q < 4; q++) acc[i][j][q] = 0.0f;

    int cur = 0;
    for (int k0 = 0; k0 < SEGL; k0 += 16) {
        bool more = (k0 + 16 < SEGL);
        if (more) {
            Ap0 += 16; Ap1 += 16;
            Bp0 += (size_t)16 * 1024; Bp1 += (size_t)16 * 1024;
            a0r = *(const float4*)Ap0; a1r = *(const float4*)Ap1;
            b0r = *(const float4*)Bp0; b1r = *(const float4*)Bp1;
            if (isD) { iv0 = invp[k0 + 16 + br]; iv1 = invp[k0 + 24 + br]; }
        }

        const uint32_t* Asu = (const uint32_t*)As[cur];
        const uint32_t* Bsu = (const uint32_t*)Bs[cur];
#pragma unroll
        for (int kb = 0; kb < 16; kb += 8) {
            uint32_t af[4][4], bf[4][2];
#pragma unroll
            for (int tm = 0; tm < 4; tm++) {
                int mb = wm * 64 + tm * 16;
                af[tm][0] = Asu[(mb + gid) * 20 + kb + tq];
                af[tm][1] = Asu[(mb + gid + 8) * 20 + kb + tq];
                af[tm][2] = Asu[(mb + gid) * 20 + kb + tq + 4];
                af[tm][3] = Asu[(mb + gid + 8) * 20 + kb + tq + 4];
            }
#pragma unroll
            for (int tn = 0; tn < 4; tn++) {
                int nb = wn * 32 + tn * 8 + gid;
                bf[tn][0] = Bsu[(kb + tq) * 136 + nb];
                bf[tn][1] = Bsu[(kb + tq + 4) * 136 + nb];
            }
#pragma unroll
            for (int tm = 0; tm < 4; tm++)
#pragma unroll
                for (int tn = 0; tn < 4; tn++)
                    mma8(acc[tm][tn], af[tm][0], af[tm][1], af[tm][2], af[tm][3],
                         bf[tn][0], bf[tn][1]);
        }

        if (more) {
            float4 nb0 = b0r, nb1 = b1r;
            if (isD) {
                nb0 = make_float4(elu1(b0r.x) * iv0, elu1(b0r.y) * iv0, elu1(b0r.z) * iv0, elu1(b0r.w) * iv0);
                nb1 = make_float4(elu1(b1r.x) * iv1, elu1(b1r.y) * iv1, elu1(b1r.z) * iv1, elu1(b1r.w) * iv1);
            }
            int nxt = cur ^ 1;
            *(float4*)(As[nxt] + ar * 20 + ac)        = cvt4tf(a0r);
            *(float4*)(As[nxt] + (ar + 64) * 20 + ac) = cvt4tf(a1r);
            *(float4*)(Bs[nxt] + br * 136 + bc)       = cvt4tf(nb0);
            *(float4*)(Bs[nxt] + (br + 8) * 136 + bc) = cvt4tf(nb1);
        }
        __syncthreads();
        cur ^= 1;
    }

#pragma unroll
    for (int tm = 0; tm < 4; tm++) {
        int row = wm * 64 + tm * 16 + gid;
#pragma unroll
        for (int tn = 0; tn < 4; tn++) {
            int col = wn * 32 + tn * 8 + 2 * tq;
            *(float2*)&C[(size_t)row * 128 + col] = make_float2(acc[tm][tn][0], acc[tm][tn][1]);
            *(float2*)&C[(size_t)(row + 8) * 128 + col] = make_float2(acc[tm][tn][2], acc[tm][tn][3]);
        }
    }
}

// -------------------- K5: recurrence, split 4x along mem columns --------------------
#define RECUR_SMEM_FLOATS (128 * 132 + 128 * 36)
__global__ __launch_bounds__(256) void recur_kernel() {
    extern __shared__ float sm[];
    float* db  = sm;               // [128][132] D staging
    float* mem = sm + 128 * 132;   // [128][36] column slab

    int bh = blockIdx.x;
    int c0 = blockIdx.y * 32;
    int t = threadIdx.x;
    int warp = t >> 5, lane = t & 31;
    int gid = lane >> 2, tq = lane & 3;
    int rowg = warp * 16 + gid;

#pragma unroll
    for (int p = 0; p < 18; p++) {
        int lin = t + p * 256;
        if (lin < 128 * 36) mem[lin] = 0.0f;
    }
    __syncthreads();

    for (int s = 0; s < NSEG; s++) {
        int mat = bh * NSEG + s;
        float* snap = g_mems + (size_t)mat * DKk * DVv;
#pragma unroll
        for (int p = 0; p < 16; p++) {
            int lin = t + p * 256;
            int row = lin >> 5, col = lin & 31;
            snap[(size_t)row * DVv + c0 + col] = mem[row * 36 + col];
        }
        if (s == NSEG - 1) break;

        const float* Dp = g_D + (size_t)mat * DKk * DVv;
#pragma unroll
        for (int p = 0; p < 64; p++) {
            int lin = t + p * 256;
            int row = lin >> 7, col = lin & 127;
            db[row * 132 + col] = Dp[lin];
        }
        __syncthreads();

        const float* P1p = g_P1 + (size_t)mat * DKk * DVv;
        float acc[4][4];
#pragma unroll
        for (int tn = 0; tn < 4; tn++) {
            int col = c0 + tn * 8 + 2 * tq;
            float2 c01 = *(const float2*)&P1p[(size_t)rowg * DVv + col];
            float2 c23 = *(const float2*)&P1p[(size_t)(rowg + 8) * DVv + col];
            acc[tn][0] = c01.x; acc[tn][1] = c01.y;
            acc[tn][2] = c23.x; acc[tn][3] = c23.y;
        }

#pragma unroll
        for (int kb = 0; kb < 16; kb++) {
            int kofs = kb * 8;
            uint32_t a0 = f2tf(-db[rowg * 132 + kofs + tq]);
            uint32_t a1 = f2tf(-db[(rowg + 8) * 132 + kofs + tq]);
            uint32_t a2 = f2tf(-db[rowg * 132 + kofs + tq + 4]);
            uint32_t a3 = f2tf(-db[(rowg + 8) * 132 + kofs + tq + 4]);
#pragma unroll
            for (int tn = 0; tn < 4; tn++) {
                int n = tn * 8 + gid;
                uint32_t b0 = f2tf(mem[(kofs + tq) * 36 + n]);
                uint32_t b1 = f2tf(mem[(kofs + tq + 4) * 36 + n]);
                mma8(acc[tn], a0, a1, a2, a3, b0, b1);
            }
        }
        __syncthreads();

#pragma unroll
        for (int tn = 0; tn < 4; tn++) {
            int col = tn * 8 + 2 * tq;
            mem[rowg * 36 + col]           += acc[tn][0];
            mem[rowg * 36 + col + 1]       += acc[tn][1];
            mem[(rowg + 8) * 36 + col]     += acc[tn][2];
            mem[(rowg + 8) * 36 + col + 1] += acc[tn][3];
        }
        __syncthreads();
    }
}

// -------------------- K6: causal flash attention (512 threads, i-tile 64) --------------------
// q/k/v are pre-rounded tf32 -> staging needs NO conversion.
#define FQKV_SMEM_FLOATS (3 * 64 * 132 + 64 * 68 + 64 * 4)
__global__ __launch_bounds__(512) void flashqkv_kernel(const float* __restrict__ betas) {
    extern __shared__ float sm[];
    float* qs = sm;
    float* ks = qs + 64 * 132;
    float* vs = ks + 64 * 132;
    float* ps = vs + 64 * 132;
    float* l4 = ps + 64 * 68;

    int bh = blockIdx.x;
    int it = 7 - blockIdx.y;
    int seg = blockIdx.z;
    int b = bh >> 3, h = bh & 7;
    int i0 = it * 64;

    int t = threadIdx.x;
    int warp = t >> 5, lane = t & 31;
    int wm = warp >> 2, wn = warp & 3;
    int gid = lane >> 2, tq = lane & 3;
    int rowg0 = wm * 16 + gid;

    const float* qbase = g_q + ((size_t)b * SS + seg * SEGL) * 1024 + h * 128;
    const float* kbase = g_k + ((size_t)b * SS + seg * SEGL) * 1024 + h * 128;
    const float* vbase = g_v + ((size_t)b * SS + seg * SEGL) * 1024 + h * 128;

    int lrow = t >> 5, lcol4 = (t & 31) * 4;

#pragma unroll
    for (int f = 0; f < 4; f++) {
        int row = lrow + f * 16;
        float4 qv = *(const float4*)(qbase + (size_t)(i0 + row) * 1024 + lcol4);
        *(float4*)(qs + row * 132 + lcol4) = qv;
    }

    float acc[4][4];
#pragma unroll
    for (int i = 0; i < 4; i++)
#pragma unroll
        for (int q = 0; q < 4; q++) acc[i][q] = 0.0f;
    float plo = 0.0f, phi = 0.0f;

    const uint32_t* qsu = (const uint32_t*)qs;
    const uint32_t* ksu = (const uint32_t*)ks;
    const uint32_t* vsu = (const uint32_t*)vs;
    const uint32_t* psu = (const uint32_t*)ps;

    float4 kreg[4], vreg[4];
#pragma unroll
    for (int f = 0; f < 4; f++) {
        int row = lrow + f * 16;
        kreg[f] = *(const float4*)(kbase + (size_t)row * 1024 + lcol4);
        vreg[f] = *(const float4*)(vbase + (size_t)row * 1024 + lcol4);
    }

    for (int jt = 0; jt <= it; jt++) {
        __syncthreads();
#pragma unroll
        for (int f = 0; f < 4; f++) {
            int row = lrow + f * 16;
            *(float4*)(ks + row * 132 + lcol4) = kreg[f];
            *(float4*)(vs + row * 132 + lcol4) = vreg[f];
        }
        __syncthreads();

        if (jt < it) {
            int j0n = (jt + 1) * 64;
#pragma unroll
            for (int f = 0; f < 4; f++) {
                int row = j0n + lrow + f * 16;
                kreg[f] = *(const float4*)(kbase + (size_t)row * 1024 + lcol4);
                vreg[f] = *(const float4*)(vbase + (size_t)row * 1024 + lcol4);
            }
        }

        int j0 = jt * 64;
        float sc[2][4];
#pragma unroll
        for (int tn = 0; tn < 2; tn++)
#pragma unroll
            for (int q = 0; q < 4; q++) sc[tn][q] = 0.0f;

#pragma unroll
        for (int kb = 0; kb < 16; kb++) {
            int kofs = kb * 8;
            uint32_t a0 = qsu[rowg0 * 132 + kofs + tq];
            uint32_t a1 = qsu[(rowg0 + 8) * 132 + kofs + tq];
            uint32_t a2 = qsu[rowg0 * 132 + kofs + tq + 4];
            uint32_t a3 = qsu[(rowg0 + 8) * 132 + kofs + tq + 4];
#pragma unroll
            for (int tn = 0; tn < 2; tn++) {
                int n = wn * 16 + tn * 8 + gid;
                uint32_t b0 = ksu[n * 132 + kofs + tq];
                uint32_t b1 = ksu[n * 132 + kofs + tq + 4];
                mma8(sc[tn], a0, a1, a2, a3, b0, b1);
            }
        }

#pragma unroll
        for (int tn = 0; tn < 2; tn++) {
            int ncol = wn * 16 + tn * 8 + 2 * tq;
            int jg0 = j0 + ncol, jg1 = j0 + ncol + 1;
            int ig_lo = i0 + rowg0, ig_hi = i0 + rowg0 + 8;
            float p0 = (jg0 <= ig_lo) ? __expf(sc[tn][0] * SCALE) : 0.0f;
            float p1 = (jg1 <= ig_lo) ? __expf(sc[tn][1] * SCALE) : 0.0f;
            float p2 = (jg0 <= ig_hi) ? __expf(sc[tn][2] * SCALE) : 0.0f;
            float p3 = (jg1 <= ig_hi) ? __expf(sc[tn][3] * SCALE) : 0.0f;
            plo += p0 + p1;
            phi += p2 + p3;
            *(float2*)(ps + rowg0 * 68 + ncol) = make_float2(ftf(p0), ftf(p1));
            *(float2*)(ps + (rowg0 + 8) * 68 + ncol) = make_float2(ftf(p2), ftf(p3));
        }
        __syncthreads();

#pragma unroll
        for (int kb = 0; kb < 8; kb++) {
            int kofs = kb * 8;
            uint32_t a0 = psu[rowg0 * 68 + kofs + tq];
            uint32_t a1 = psu[(rowg0 + 8) * 68 + kofs + tq];
            uint32_t a2 = psu[rowg0 * 68 + kofs + tq + 4];
            uint32_t a3 = psu[(rowg0 + 8) * 68 + kofs + tq + 4];
#pragma unroll
            for (int tn = 0; tn < 4; tn++) {
                int n = wn * 32 + tn * 8 + gid;
                uint32_t b0 = vsu[(kofs + tq) * 132 + n];
                uint32_t b1 = vsu[(kofs + tq + 4) * 132 + n];
                mma8(acc[tn], a0, a1, a2, a3, b0, b1);
            }
        }
    }

    plo += __shfl_xor_sync(0xffffffffu, plo, 1);
    plo += __shfl_xor_sync(0xffffffffu, plo, 2);
    phi += __shfl_xor_sync(0xffffffffu, phi, 1);
    phi += __shfl_xor_sync(0xffffffffu, phi, 2);
    if (tq == 0) {
        l4[rowg0 * 4 + wn] = plo;
        l4[(rowg0 + 8) * 4 + wn] = phi;
    }
    __syncthreads();

    float invl_lo = 1.0f / (l4[rowg0 * 4] + l4[rowg0 * 4 + 1] + l4[rowg0 * 4 + 2] + l4[rowg0 * 4 + 3]);
    float invl_hi = 1.0f / (l4[(rowg0 + 8) * 4] + l4[(rowg0 + 8) * 4 + 1] + l4[(rowg0 + 8) * 4 + 2] + l4[(rowg0 + 8) * 4 + 3]);

    float* outbase = g_att + ((size_t)b * SS + seg * SEGL + i0) * 1024 + h * 128;
#pragma unroll
    for (int tn = 0; tn < 4; tn++) {
        int col = wn * 32 + tn * 8 + 2 * tq;
        float be0 = __ldg(betas + h * 128 + col);
        float be1 = __ldg(betas + h * 128 + col + 1);
        float g0 = 1.0f / (1.0f + __expf(-be0));
        float g1 = 1.0f / (1.0f + __expf(-be1));
        float o0 = (1.0f - g0) * acc[tn][0] * invl_lo;
        float o1 = (1.0f - g1) * acc[tn][1] * invl_lo;
        float o2 = (1.0f - g0) * acc[tn][2] * invl_hi;
        float o3 = (1.0f - g1) * acc[tn][3] * invl_hi;
        *(float2*)(outbase + (size_t)rowg0 * 1024 + col) = make_float2(o0, o1);
        *(float2*)(outbase + (size_t)(rowg0 + 8) * 1024 + col) = make_float2(o2, o3);
    }
}

// -------------------- K7: mix — att += g * (sigma_q @ mem) / dn  (segs 1..7; RMW) --------------------
#define MIX_SMEM_FLOATS (64 * 132 + 128 * 132 + 64 + 128)
__global__ __launch_bounds__(256) void mix_kernel(const float* __restrict__ betas) {
    extern __shared__ float sm[];
    float* qs = sm;                 // 64x132 sigma_q (tf32)
    float* ms = qs + 64 * 132;      // 128x132 mem (tf32)
    float* dn = ms + 128 * 132;     // 64
    float* zs = dn + 64;            // 128

    int bh = blockIdx.x;
    int it = blockIdx.y;
    int seg = blockIdx.z + 1;       // 1..7
    int b = bh >> 3, h = bh & 7;
    int mat = bh * NSEG + seg;
    int i0 = it * 64;

    int t = threadIdx.x;
    int warp = t >> 5, lane = t & 31;
    int wm = warp >> 1, wn = warp & 1;
    int gid = lane >> 2, tq = lane & 3;
    int rowg0 = wm * 16 + gid;

    const float* qbase = g_q + ((size_t)b * SS + seg * SEGL) * 1024 + h * 128;
    const float* memp  = g_mems + (size_t)mat * DKk * DVv;

    if (t < 128) zs[t] = g_zall[mat * DKk + t];

    int lrow = t >> 5, lcol4 = (t & 31) * 4;
#pragma unroll
    for (int f = 0; f < 8; f++) {
        int row = lrow + f * 8;
        float4 qv = *(const float4*)(qbase + (size_t)(i0 + row) * 1024 + lcol4);
        // q already tf32 -> elu then round (same values as before)
        qv.x = ftf(elu1(qv.x));
        qv.y = ftf(elu1(qv.y));
        qv.z = ftf(elu1(qv.z));
        qv.w = ftf(elu1(qv.w));
        *(float4*)(qs + row * 132 + lcol4) = qv;
    }
#pragma unroll
    for (int f = 0; f < 16; f++) {
        int row = lrow + f * 8;
        float4 mv = *(const float4*)(memp + (size_t)row * 128 + lcol4);
        *(float4*)(ms + row * 132 + lcol4) = cvt4tf(mv);
    }
    __syncthreads();

    if (t < 64) {
        float d = 0.0f;
#pragma unroll 8
        for (int kc = 0; kc < 128; kc++) d += qs[t * 132 + kc] * zs[kc];
        dn[t] = d;
    }
    __syncthreads();

    const uint32_t* qsu = (const uint32_t*)qs;
    const uint32_t* msu = (const uint32_t*)ms;

    float accm[8][4];
#pragma unroll
    for (int i = 0; i < 8; i++)
#pragma unroll
        for (int q = 0; q < 4; q++) accm[i][q] = 0.0f;

#pragma unroll
    for (int kb = 0; kb < 16; kb++) {
        int kofs = kb * 8;
        uint32_t a0 = qsu[rowg0 * 132 + kofs + tq];
        uint32_t a1 = qsu[(rowg0 + 8) * 132 + kofs + tq];
        uint32_t a2 = qsu[rowg0 * 132 + kofs + tq + 4];
        uint32_t a3 = qsu[(rowg0 + 8) * 132 + kofs + tq + 4];
#pragma unroll
        for (int tn = 0; tn < 8; tn++) {
            int n = wn * 64 + tn * 8 + gid;
            uint32_t b0 = msu[(kofs + tq) * 132 + n];
            uint32_t b1 = msu[(kofs + tq + 4) * 132 + n];
            mma8(accm[tn], a0, a1, a2, a3, b0, b1);
        }
    }

    float invd_lo = 1.0f / dn[rowg0];
    float invd_hi = 1.0f / dn[rowg0 + 8];

    float* outbase = g_att + ((size_t)b * SS + seg * SEGL + i0) * 1024 + h * 128;
#pragma unroll
    for (int tn = 0; tn < 8; tn++) {
        int col = wn * 64 + tn * 8 + 2 * tq;
        float be0 = __ldg(betas + h * 128 + col);
        float be1 = __ldg(betas + h * 128 + col + 1);
        float g0 = 1.0f / (1.0f + __expf(-be0));
        float g1 = 1.0f / (1.0f + __expf(-be1));
        float2 lo = *(float2*)(outbase + (size_t)rowg0 * 1024 + col);
        float2 hi = *(float2*)(outbase + (size_t)(rowg0 + 8) * 1024 + col);
        lo.x += g0 * accm[tn][0] * invd_lo;
        lo.y += g1 * accm[tn][1] * invd_lo;
        hi.x += g0 * accm[tn][2] * invd_hi;
        hi.y += g1 * accm[tn][3] * invd_hi;
        *(float2*)(outbase + (size_t)rowg0 * 1024 + col) = lo;
        *(float2*)(outbase + (size_t)(rowg0 + 8) * 1024 + col) = hi;
    }
}

// -------------------- launch (fork-join capture graph) --------------------
extern "C" void kernel_launch(void* const* d_in, const int* in_sizes, int n_in,
                              void* d_out, int out_size) {
    const float* x     = (const float*)d_in[0];
    const float* Wk    = (const float*)d_in[1];
    const float* Wv    = (const float*)d_in[2];
    const float* Wq    = (const float*)d_in[3];
    const float* Wout  = (const float*)d_in[4];
    const float* betas = (const float*)d_in[5];
    float* out = (float*)d_out;

    cudaFuncSetAttribute(recur_kernel, cudaFuncAttributeMaxDynamicSharedMemorySize,
                         RECUR_SMEM_FLOATS * (int)sizeof(float));
    cudaFuncSetAttribute(flashqkv_kernel, cudaFuncAttributeMaxDynamicSharedMemorySize,
                         FQKV_SMEM_FLOATS * (int)sizeof(float));
    cudaFuncSetAttribute(mix_kernel, cudaFuncAttributeMaxDynamicSharedMemorySize,
                         MIX_SMEM_FLOATS * (int)sizeof(float));

    cudaStream_t s2;
    cudaStreamCreate(&s2);
    cudaEvent_t e1, e2;
    cudaEventCreateWithFlags(&e1, cudaEventDisableTiming);
    cudaEventCreateWithFlags(&e2, cudaEventDisableTiming);

    proj_mma<<<dim3(64, 8, 3), 256>>>(x, Wq, Wk, Wv);

    // fork: sigma_k pipeline on side stream
    cudaEventRecord(e1, 0);
    cudaStreamWaitEvent(s2, e1, 0);
    sig_kernel<<<dim3(BH, NSEG, 8), 256, 0, s2>>>();
    zprefix_kernel<<<BH, 128, 0, s2>>>();
    dn_kernel<<<dim3(MATS, 4), 128, 0, s2>>>();
    pd_kernel<<<dim3(MATS, 2), 256, 0, s2>>>();
    recur_kernel<<<dim3(BH, 4), 256, RECUR_SMEM_FLOATS * sizeof(float), s2>>>();
    cudaEventRecord(e2, s2);

    // concurrently: causal attention (long pole) on main stream
    flashqkv_kernel<<<dim3(BH, 8, 8), 512, FQKV_SMEM_FLOATS * sizeof(float)>>>(betas);

    // join, then memory-read mix and output GEMM
    cudaStreamWaitEvent(0, e2, 0);
    mix_kernel<<<dim3(BH, 8, 7), 256, MIX_SMEM_FLOATS * sizeof(float)>>>(betas);
    out_mma<<<dim3(64, 8), 256>>>(Wout, out);
}

// round 16
// speedup vs baseline: 1.0062x; 1.0062x over previous
#include <cuda_runtime.h>
#include <cstdint>

#define BB 2
#define SS 4096
#define DD 1024
#define HH 8
#define DKk 128
#define DVv 128
#define SEGL 512
#define NSEG 8
#define BH (BB*HH)
#define MATS (BH*NSEG)   // 128

#define SCALE 0.08838834764831845f  // 1/sqrt(128)

// -------------------- scratch --------------------
__device__ float g_q[(size_t)BB*SS*HH*DKk];
__device__ float g_k[(size_t)BB*SS*HH*DKk];
__device__ float g_v[(size_t)BB*SS*HH*DVv];
__device__ float g_att[(size_t)BB*SS*HH*DVv];
__device__ float g_skT[(size_t)MATS*DKk*SEGL];
__device__ float g_P1[(size_t)MATS*DKk*DVv];
__device__ float g_D [(size_t)MATS*DKk*DVv];
__device__ float g_mems[(size_t)MATS*DKk*DVv];
__device__ float g_zall[MATS*DKk];
__device__ float g_zsp[MATS*8*DKk];
__device__ float g_dnv[MATS*SEGL];

// -------------------- tf32 helpers --------------------
__device__ __forceinline__ uint32_t f2tf(float f) {
    uint32_t u; asm("cvt.rna.tf32.f32 %0, %1;" : "=r"(u) : "f"(f)); return u;
}
__device__ __forceinline__ float ftf(float f) { return __uint_as_float(f2tf(f)); }
__device__ __forceinline__ float4 cvt4tf(float4 v) {
    float4 r;
    r.x = ftf(v.x); r.y = ftf(v.y); r.z = ftf(v.z); r.w = ftf(v.w);
    return r;
}
__device__ __forceinline__ void mma8(float* c, uint32_t a0, uint32_t a1, uint32_t a2, uint32_t a3,
                                     uint32_t b0, uint32_t b1) {
    asm volatile("mma.sync.aligned.m16n8k8.row.col.f32.tf32.tf32.f32 "
                 "{%0,%1,%2,%3}, {%4,%5,%6,%7}, {%8,%9}, {%0,%1,%2,%3};"
                 : "+f"(c[0]), "+f"(c[1]), "+f"(c[2]), "+f"(c[3])
                 : "r"(a0), "r"(a1), "r"(a2), "r"(a3), "r"(b0), "r"(b1));
}
__device__ __forceinline__ float elu1(float x) { return (x > 0.0f) ? x + 1.0f : __expf(x); }

// -------------------- generic 128x128 CTA tf32 GEMM body (2-stage pipeline) --------------------
template<int K>
__device__ __forceinline__ void gemm_body(const float* __restrict__ A, int lda,
                                          const float* __restrict__ Bb, int ldb,
                                          float* __restrict__ C, int ldc,
                                          int n0, int m0) {
    __shared__ float As[2][128 * 20];
    __shared__ float Bs[2][16 * 136];

    int t = threadIdx.x;
    int ar = t >> 2, ac = (t & 3) * 4;
    int br = t >> 5, bc = (t & 31) * 4;
    int warp = t >> 5, lane = t & 31;
    int wm = warp >> 2, wn = warp & 3;
    int gid = lane >> 2, tq = lane & 3;

    const float* Ap0 = A + (size_t)(m0 + ar) * lda + ac;
    const float* Ap1 = Ap0 + (size_t)64 * lda;
    const float* Bp0 = Bb + (size_t)br * ldb + bc;
    const float* Bp1 = Bp0 + (size_t)8 * ldb;

    float4 a0r = *(const float4*)Ap0;
    float4 a1r = *(const float4*)Ap1;
    float4 b0r = *(const float4*)Bp0;
    float4 b1r = *(const float4*)Bp1;

    *(float4*)(As[0] + ar * 20 + ac)        = cvt4tf(a0r);
    *(float4*)(As[0] + (ar + 64) * 20 + ac) = cvt4tf(a1r);
    *(float4*)(Bs[0] + br * 136 + bc)       = cvt4tf(b0r);
    *(float4*)(Bs[0] + (br + 8) * 136 + bc) = cvt4tf(b1r);
    __syncthreads();

    float acc[4][4][4];
#pragma unroll
    for (int i = 0; i < 4; i++)
#pragma unroll
        for (int j = 0; j < 4; j++)
#pragma unroll
            for (int q = 0; q < 4; q++) acc[i][j][q] = 0.0f;

    int cur = 0;
    for (int k0 = 0; k0 < K; k0 += 16) {
        bool more = (k0 + 16 < K);
        if (more) {
            Ap0 += 16; Ap1 += 16;
            Bp0 += (size_t)16 * ldb; Bp1 += (size_t)16 * ldb;
            a0r = *(const float4*)Ap0; a1r = *(const float4*)Ap1;
            b0r = *(const float4*)Bp0; b1r = *(const float4*)Bp1;
        }

        const uint32_t* Asu = (const uint32_t*)As[cur];
        const uint32_t* Bsu = (const uint32_t*)Bs[cur];
#pragma unroll
        for (int kb = 0; kb < 16; kb += 8) {
            uint32_t af[4][4], bf[4][2];
#pragma unroll
            for (int tm = 0; tm < 4; tm++) {
                int mb = wm * 64 + tm * 16;
                af[tm][0] = Asu[(mb + gid) * 20 + kb + tq];
                af[tm][1] = Asu[(mb + gid + 8) * 20 + kb + tq];
                af[tm][2] = Asu[(mb + gid) * 20 + kb + tq + 4];
                af[tm][3] = Asu[(mb + gid + 8) * 20 + kb + tq + 4];
            }
#pragma unroll
            for (int tn = 0; tn < 4; tn++) {
                int nb = wn * 32 + tn * 8 + gid;
                bf[tn][0] = Bsu[(kb + tq) * 136 + nb];
                bf[tn][1] = Bsu[(kb + tq + 4) * 136 + nb];
            }
#pragma unroll
            for (int tm = 0; tm < 4; tm++)
#pragma unroll
                for (int tn = 0; tn < 4; tn++)
                    mma8(acc[tm][tn], af[tm][0], af[tm][1], af[tm][2], af[tm][3],
                         bf[tn][0], bf[tn][1]);
        }

        if (more) {
            int nxt = cur ^ 1;
            *(float4*)(As[nxt] + ar * 20 + ac)        = cvt4tf(a0r);
            *(float4*)(As[nxt] + (ar + 64) * 20 + ac) = cvt4tf(a1r);
            *(float4*)(Bs[nxt] + br * 136 + bc)       = cvt4tf(b0r);
            *(float4*)(Bs[nxt] + (br + 8) * 136 + bc) = cvt4tf(b1r);
        }
        __syncthreads();
        cur ^= 1;
    }

#pragma unroll
    for (int tm = 0; tm < 4; tm++) {
        int row = m0 + wm * 64 + tm * 16 + gid;
#pragma unroll
        for (int tn = 0; tn < 4; tn++) {
            int col = n0 + wn * 32 + tn * 8 + 2 * tq;
            *(float2*)&C[(size_t)row * ldc + col] = make_float2(acc[tm][tn][0], acc[tm][tn][1]);
            *(float2*)&C[(size_t)(row + 8) * ldc + col] = make_float2(acc[tm][tn][2], acc[tm][tn][3]);
        }
    }
}

__global__ __launch_bounds__(256) void proj_mma(const float* __restrict__ x,
                                                const float* __restrict__ Wq,
                                                const float* __restrict__ Wk,
                                                const float* __restrict__ Wv) {
    const float* W = (blockIdx.z == 0) ? Wq : (blockIdx.z == 1) ? Wk : Wv;
    float* C = (blockIdx.z == 0) ? g_q : (blockIdx.z == 1) ? g_k : g_v;
    gemm_body<1024>(x, 1024, W + (size_t)blockIdx.y * 131072, 128,
                    C, 1024, blockIdx.y * 128, blockIdx.x * 128);
}

// out over segment-0 rows only (m-tiles 0..3 and 32..35) — depends only on flash
__global__ __launch_bounds__(256) void out_seg0_mma(const float* __restrict__ Wout,
                                                    float* __restrict__ C) {
    int x = blockIdx.x;                       // 0..7
    int mt = (x < 4) ? x : (x + 28);          // 0..3, 32..35
    gemm_body<1024>(g_att, 1024, Wout + (size_t)blockIdx.y * 128, 1024,
                    C, 1024, blockIdx.y * 128, mt * 128);
}

// out over the remaining 56 m-tiles — depends on mix
__global__ __launch_bounds__(256) void out_rest_mma(const float* __restrict__ Wout,
                                                    float* __restrict__ C) {
    int x = blockIdx.x;                       // 0..55
    int mt = (x < 28) ? (x + 4) : (x + 8);    // 4..31, 36..63
    gemm_body<1024>(g_att, 1024, Wout + (size_t)blockIdx.y * 128, 1024,
                    C, 1024, blockIdx.y * 128, mt * 128);
}

// -------------------- K1: sigma_k + transpose + z partials --------------------
__global__ __launch_bounds__(256) void sig_kernel() {
    __shared__ float sm[64 * 132];
    int bh = blockIdx.x, seg = blockIdx.y, stile = blockIdx.z;
    int b = bh >> 3, h = bh & 7;
    int mat = bh * NSEG + seg;
    int s0 = stile * 64;
    int t = threadIdx.x;

    const float* kbase = g_k + ((size_t)b * SS + seg * SEGL + s0) * 1024 + h * 128;
#pragma unroll
    for (int p = 0; p < 32; p++) {
        int lin = t + p * 256;
        int row = lin >> 7, col = lin & 127;
        sm[row * 132 + col] = elu1(kbase[(size_t)row * 1024 + col]);
    }
    __syncthreads();

    float* skT = g_skT + (size_t)mat * DKk * SEGL;
#pragma unroll
    for (int p = 0; p < 32; p++) {
        int lin = t + p * 256;
        int kc = lin >> 6, scol = lin & 63;
        skT[(size_t)kc * SEGL + s0 + scol] = sm[scol * 132 + kc];
    }
    if (t < 128) {
        float zs = 0.0f;
#pragma unroll 8
        for (int s = 0; s < 64; s++) zs += sm[s * 132 + t];
        g_zsp[(mat * 8 + stile) * DKk + t] = zs;
    }
}

// -------------------- K2: z prefix --------------------
__global__ void zprefix_kernel() {
    int bh = blockIdx.x, t = threadIdx.x;  // block 128
    float z = 1.0f / (float)DKk;
    for (int s = 0; s < NSEG; s++) {
        int mat = bh * NSEG + s;
        g_zall[mat * DKk + t] = z;
#pragma unroll
        for (int st = 0; st < 8; st++) z += g_zsp[(mat * 8 + st) * DKk + t];
    }
}

// -------------------- K3: per-token 1/dn (grid split x4) --------------------
__global__ __launch_bounds__(128) void dn_kernel() {
    __shared__ float zs[128];
    int mat = blockIdx.x;
    int s0 = blockIdx.y * 128;
    int bh = mat >> 3, seg = mat & 7;
    int b = bh >> 3, h = bh & 7;
    int t = threadIdx.x;
    zs[t] = g_zall[mat * DKk + t];
    __syncthreads();
    const float* kr = g_k + ((size_t)b * SS + seg * SEGL + s0 + t) * 1024 + h * 128;
    float d = 0.0f;
#pragma unroll 8
    for (int i = 0; i < 32; i++) {
        float4 v = *(const float4*)(kr + i * 4);
        d += elu1(v.x) * zs[i * 4 + 0];
        d += elu1(v.y) * zs[i * 4 + 1];
        d += elu1(v.z) * zs[i * 4 + 2];
        d += elu1(v.w) * zs[i * 4 + 3];
    }
    g_dnv[mat * SEGL + s0 + t] = 1.0f / d;
}

// -------------------- K4: P1 and D GEMMs --------------------
__global__ __launch_bounds__(256) void pd_kernel() {
    __shared__ float As[2][128 * 20];
    __shared__ float Bs[2][16 * 136];

    int mat = blockIdx.x;
    bool isD = (blockIdx.y == 1);
    int bh = mat >> 3, seg = mat & 7;
    int b = bh >> 3, h = bh & 7;

    const float* A = g_skT + (size_t)mat * DKk * SEGL;
    const float* Bb = (isD ? g_k : g_v) + ((size_t)b * SS + seg * SEGL) * 1024 + h * 128;
    float* C = (isD ? g_D : g_P1) + (size_t)mat * DKk * DVv;
    const float* invp = g_dnv + mat * SEGL;

    int t = threadIdx.x;
    int ar = t >> 2, ac = (t & 3) * 4;
    int br = t >> 5, bc = (t & 31) * 4;
    int warp = t >> 5, lane = t & 31;
    int wm = warp >> 2, wn = warp & 3;
    int gid = lane >> 2, tq = lane & 3;

    const float* Ap0 = A + (size_t)ar * SEGL + ac;
    const float* Ap1 = Ap0 + (size_t)64 * SEGL;
    const float* Bp0 = Bb + (size_t)br * 1024 + bc;
    const float* Bp1 = Bp0 + (size_t)8 * 1024;

    float4 a0r = *(const float4*)Ap0;
    float4 a1r = *(const float4*)Ap1;
    float4 b0r = *(const float4*)Bp0;
    float4 b1r = *(const float4*)Bp1;
    float iv0 = isD ? invp[br] : 1.0f;
    float iv1 = isD ? invp[8 + br] : 1.0f;

    float4 tb0 = b0r, tb1 = b1r;
    if (isD) {
        tb0 = make_float4(elu1(b0r.x) * iv0, elu1(b0r.y) * iv0, elu1(b0r.z) * iv0, elu1(b0r.w) * iv0);
        tb1 = make_float4(elu1(b1r.x) * iv1, elu1(b1r.y) * iv1, elu1(b1r.z) * iv1, elu1(b1r.w) * iv1);
    }
    *(float4*)(As[0] + ar * 20 + ac)        = cvt4tf(a0r);
    *(float4*)(As[0] + (ar + 64) * 20 + ac) = cvt4tf(a1r);
    *(float4*)(Bs[0] + br * 136 + bc)       = cvt4tf(tb0);
    *(float4*)(Bs[0] + (br + 8) * 136 + bc) = cvt4tf(tb1);
    __syncthreads();

    float acc[4][4][4];
#pragma unroll
    for (int i = 0; i < 4; i++)
#pragma unroll
        for (int j = 0; j < 4; j++)
#pragma unroll
            for (int q = 0; q < 4; q++) acc[i][j][q] = 0.0f;

    int cur = 0;
    for (int k0 = 0; k0 < SEGL; k0 += 16) {
        bool more = (k0 + 16 < SEGL);
        if (more) {
            Ap0 += 16; Ap1 += 16;
            Bp0 += (size_t)16 * 1024; Bp1 += (size_t)16 * 1024;
            a0r = *(const float4*)Ap0; a1r = *(const float4*)Ap1;
            b0r = *(const float4*)Bp0; b1r = *(const float4*)Bp1;
            if (isD) { iv0 = invp[k0 + 16 + br]; iv1 = invp[k0 + 24 + br]; }
        }

        const uint32_t* Asu = (const uint32_t*)As[cur];
        const uint32_t* Bsu = (const uint32_t*)Bs[cur];
#pragma unroll
        for (int kb = 0; kb < 16; kb += 8) {
            uint32_t af[4][4], bf[4][2];
#pragma unroll
            for (int tm = 0; tm < 4; tm++) {
                int mb = wm * 64 + tm * 16;
                af[tm][0] = Asu[(mb + gid) * 20 + kb + tq];
                af[tm][1] = Asu[(mb + gid + 8) * 20 + kb + tq];
                af[tm][2] = Asu[(mb + gid) * 20 + kb + tq + 4];
                af[tm][3] = Asu[(mb + gid + 8) * 20 + kb + tq + 4];
            }
#pragma unroll
            for (int tn = 0; tn < 4; tn++) {
                int nb = wn * 32 + tn * 8 + gid;
                bf[tn][0] = Bsu[(kb + tq) * 136 + nb];
                bf[tn][1] = Bsu[(kb + tq + 4) * 136 + nb];
            }
#pragma unroll
            for (int tm = 0; tm < 4; tm++)
#pragma unroll
                for (int tn = 0; tn < 4; tn++)
                    mma8(acc[tm][tn], af[tm][0], af[tm][1], af[tm][2], af[tm][3],
                         bf[tn][0], bf[tn][1]);
        }

        if (more) {
            float4 nb0 = b0r, nb1 = b1r;
            if (isD) {
                nb0 = make_float4(elu1(b0r.x) * iv0, elu1(b0r.y) * iv0, elu1(b0r.z) * iv0, elu1(b0r.w) * iv0);
                nb1 = make_float4(elu1(b1r.x) * iv1, elu1(b1r.y) * iv1, elu1(b1r.z) * iv1, elu1(b1r.w) * iv1);
            }
            int nxt = cur ^ 1;
            *(float4*)(As[nxt] + ar * 20 + ac)        = cvt4tf(a0r);
            *(float4*)(As[nxt] + (ar + 64) * 20 + ac) = cvt4tf(a1r);
            *(float4*)(Bs[nxt] + br * 136 + bc)       = cvt4tf(nb0);
            *(float4*)(Bs[nxt] + (br + 8) * 136 + bc) = cvt4tf(nb1);
        }
        __syncthreads();
        cur ^= 1;
    }

#pragma unroll
    for (int tm = 0; tm < 4; tm++) {
        int row = wm * 64 + tm * 16 + gid;
#pragma unroll
        for (int tn = 0; tn < 4; tn++) {
            int col = wn * 32 + tn * 8 + 2 * tq;
            *(float2*)&C[(size_t)row * 128 + col] = make_float2(acc[tm][tn][0], acc[tm][tn][1]);
            *(float2*)&C[(size_t)(row + 8) * 128 + col] = make_float2(acc[tm][tn][2], acc[tm][tn][3]);
        }
    }
}

// -------------------- K5: recurrence, split 4x along mem columns --------------------
#define RECUR_SMEM_FLOATS (128 * 132 + 128 * 36)
__global__ __launch_bounds__(256) void recur_kernel() {
    extern __shared__ float sm[];
    float* db  = sm;               // [128][132] D staging
    float* mem = sm + 128 * 132;   // [128][36] column slab

    int bh = blockIdx.x;
    int c0 = blockIdx.y * 32;
    int t = threadIdx.x;
    int warp = t >> 5, lane = t & 31;
    int gid = lane >> 2, tq = lane & 3;
    int rowg = warp * 16 + gid;

#pragma unroll
    for (int p = 0; p < 18; p++) {
        int lin = t + p * 256;
        if (lin < 128 * 36) mem[lin] = 0.0f;
    }
    __syncthreads();

    for (int s = 0; s < NSEG; s++) {
        int mat = bh * NSEG + s;
        float* snap = g_mems + (size_t)mat * DKk * DVv;
#pragma unroll
        for (int p = 0; p < 16; p++) {
            int lin = t + p * 256;
            int row = lin >> 5, col = lin & 31;
            snap[(size_t)row * DVv + c0 + col] = mem[row * 36 + col];
        }
        if (s == NSEG - 1) break;

        const float* Dp = g_D + (size_t)mat * DKk * DVv;
#pragma unroll
        for (int p = 0; p < 64; p++) {
            int lin = t + p * 256;
            int row = lin >> 7, col = lin & 127;
            db[row * 132 + col] = Dp[lin];
        }
        __syncthreads();

        const float* P1p = g_P1 + (size_t)mat * DKk * DVv;
        float acc[4][4];
#pragma unroll
        for (int tn = 0; tn < 4; tn++) {
            int col = c0 + tn * 8 + 2 * tq;
            float2 c01 = *(const float2*)&P1p[(size_t)rowg * DVv + col];
            float2 c23 = *(const float2*)&P1p[(size_t)(rowg + 8) * DVv + col];
            acc[tn][0] = c01.x; acc[tn][1] = c01.y;
            acc[tn][2] = c23.x; acc[tn][3] = c23.y;
        }

#pragma unroll
        for (int kb = 0; kb < 16; kb++) {
            int kofs = kb * 8;
            uint32_t a0 = f2tf(-db[rowg * 132 + kofs + tq]);
            uint32_t a1 = f2tf(-db[(rowg + 8) * 132 + kofs + tq]);
            uint32_t a2 = f2tf(-db[rowg * 132 + kofs + tq + 4]);
            uint32_t a3 = f2tf(-db[(rowg + 8) * 132 + kofs + tq + 4]);
#pragma unroll
            for (int tn = 0; tn < 4; tn++) {
                int n = tn * 8 + gid;
                uint32_t b0 = f2tf(mem[(kofs + tq) * 36 + n]);
                uint32_t b1 = f2tf(mem[(kofs + tq + 4) * 36 + n]);
                mma8(acc[tn], a0, a1, a2, a3, b0, b1);
            }
        }
        __syncthreads();

#pragma unroll
        for (int tn = 0; tn < 4; tn++) {
            int col = tn * 8 + 2 * tq;
            mem[rowg * 36 + col]           += acc[tn][0];
            mem[rowg * 36 + col + 1]       += acc[tn][1];
            mem[(rowg + 8) * 36 + col]     += acc[tn][2];
            mem[(rowg + 8) * 36 + col + 1] += acc[tn][3];
        }
        __syncthreads();
    }
}

// -------------------- K6: causal flash attention (512 threads, i-tile 64) --------------------
#define FQKV_SMEM_FLOATS (3 * 64 * 132 + 64 * 68 + 64 * 4)
__global__ __launch_bounds__(512) void flashqkv_kernel(const float* __restrict__ betas) {
    extern __shared__ float sm[];
    float* qs = sm;
    float* ks = qs + 64 * 132;
    float* vs = ks + 64 * 132;
    float* ps = vs + 64 * 132;
    float* l4 = ps + 64 * 68;

    int bh = blockIdx.x;
    int it = 7 - blockIdx.y;
    int seg = blockIdx.z;
    int b = bh >> 3, h = bh & 7;
    int i0 = it * 64;

    int t = threadIdx.x;
    int warp = t >> 5, lane = t & 31;
    int wm = warp >> 2, wn = warp & 3;
    int gid = lane >> 2, tq = lane & 3;
    int rowg0 = wm * 16 + gid;

    const float* qbase = g_q + ((size_t)b * SS + seg * SEGL) * 1024 + h * 128;
    const float* kbase = g_k + ((size_t)b * SS + seg * SEGL) * 1024 + h * 128;
    const float* vbase = g_v + ((size_t)b * SS + seg * SEGL) * 1024 + h * 128;

    int lrow = t >> 5, lcol4 = (t & 31) * 4;

#pragma unroll
    for (int f = 0; f < 4; f++) {
        int row = lrow + f * 16;
        float4 qv = *(const float4*)(qbase + (size_t)(i0 + row) * 1024 + lcol4);
        *(float4*)(qs + row * 132 + lcol4) = cvt4tf(qv);
    }

    float acc[4][4];
#pragma unroll
    for (int i = 0; i < 4; i++)
#pragma unroll
        for (int q = 0; q < 4; q++) acc[i][q] = 0.0f;
    float plo = 0.0f, phi = 0.0f;

    const uint32_t* qsu = (const uint32_t*)qs;
    const uint32_t* ksu = (const uint32_t*)ks;
    const uint32_t* vsu = (const uint32_t*)vs;
    const uint32_t* psu = (const uint32_t*)ps;

    float4 kreg[4], vreg[4];
#pragma unroll
    for (int f = 0; f < 4; f++) {
        int row = lrow + f * 16;
        kreg[f] = *(const float4*)(kbase + (size_t)row * 1024 + lcol4);
        vreg[f] = *(const float4*)(vbase + (size_t)row * 1024 + lcol4);
    }

    for (int jt = 0; jt <= it; jt++) {
        __syncthreads();
#pragma unroll
        for (int f = 0; f < 4; f++) {
            int row = lrow + f * 16;
            *(float4*)(ks + row * 132 + lcol4) = cvt4tf(kreg[f]);
            *(float4*)(vs + row * 132 + lcol4) = cvt4tf(vreg[f]);
        }
        __syncthreads();

        if (jt < it) {
            int j0n = (jt + 1) * 64;
#pragma unroll
            for (int f = 0; f < 4; f++) {
                int row = j0n + lrow + f * 16;
                kreg[f] = *(const float4*)(kbase + (size_t)row * 1024 + lcol4);
                vreg[f] = *(const float4*)(vbase + (size_t)row * 1024 + lcol4);
            }
        }

        int j0 = jt * 64;
        float sc[2][4];
#pragma unroll
        for (int tn = 0; tn < 2; tn++)
#pragma unroll
            for (int q = 0; q < 4; q++) sc[tn][q] = 0.0f;

#pragma unroll
        for (int kb = 0; kb < 16; kb++) {
            int kofs = kb * 8;
            uint32_t a0 = qsu[rowg0 * 132 + kofs + tq];
            uint32_t a1 = qsu[(rowg0 + 8) * 132 + kofs + tq];
            uint32_t a2 = qsu[rowg0 * 132 + kofs + tq + 4];
            uint32_t a3 = qsu[(rowg0 + 8) * 132 + kofs + tq + 4];
#pragma unroll
            for (int tn = 0; tn < 2; tn++) {
                int n = wn * 16 + tn * 8 + gid;
                uint32_t b0 = ksu[n * 132 + kofs + tq];
                uint32_t b1 = ksu[n * 132 + kofs + tq + 4];
                mma8(sc[tn], a0, a1, a2, a3, b0, b1);
            }
        }

#pragma unroll
        for (int tn = 0; tn < 2; tn++) {
            int ncol = wn * 16 + tn * 8 + 2 * tq;
            int jg0 = j0 + ncol, jg1 = j0 + ncol + 1;
            int ig_lo = i0 + rowg0, ig_hi = i0 + rowg0 + 8;
            float p0 = (jg0 <= ig_lo) ? __expf(sc[tn][0] * SCALE) : 0.0f;
            float p1 = (jg1 <= ig_lo) ? __expf(sc[tn][1] * SCALE) : 0.0f;
            float p2 = (jg0 <= ig_hi) ? __expf(sc[tn][2] * SCALE) : 0.0f;
            float p3 = (jg1 <= ig_hi) ? __expf(sc[tn][3] * SCALE) : 0.0f;
            plo += p0 + p1;
            phi += p2 + p3;
            *(float2*)(ps + rowg0 * 68 + ncol) = make_float2(ftf(p0), ftf(p1));
            *(float2*)(ps + (rowg0 + 8) * 68 + ncol) = make_float2(ftf(p2), ftf(p3));
        }
        __syncthreads();

#pragma unroll
        for (int kb = 0; kb < 8; kb++) {
            int kofs = kb * 8;
            uint32_t a0 = psu[rowg0 * 68 + kofs + tq];
            uint32_t a1 = psu[(rowg0 + 8) * 68 + kofs + tq];
            uint32_t a2 = psu[rowg0 * 68 + kofs + tq + 4];
            uint32_t a3 = psu[(rowg0 + 8) * 68 + kofs + tq + 4];
#pragma unroll
            for (int tn = 0; tn < 4; tn++) {
                int n = wn * 32 + tn * 8 + gid;
                uint32_t b0 = vsu[(kofs + tq) * 132 + n];
                uint32_t b1 = vsu[(kofs + tq + 4) * 132 + n];
                mma8(acc[tn], a0, a1, a2, a3, b0, b1);
            }
        }
    }

    plo += __shfl_xor_sync(0xffffffffu, plo, 1);
    plo += __shfl_xor_sync(0xffffffffu, plo, 2);
    phi += __shfl_xor_sync(0xffffffffu, phi, 1);
    phi += __shfl_xor_sync(0xffffffffu, phi, 2);
    if (tq == 0) {
        l4[rowg0 * 4 + wn] = plo;
        l4[(rowg0 + 8) * 4 + wn] = phi;
    }
    __syncthreads();

    float invl_lo = 1.0f / (l4[rowg0 * 4] + l4[rowg0 * 4 + 1] + l4[rowg0 * 4 + 2] + l4[rowg0 * 4 + 3]);
    float invl_hi = 1.0f / (l4[(rowg0 + 8) * 4] + l4[(rowg0 + 8) * 4 + 1] + l4[(rowg0 + 8) * 4 + 2] + l4[(rowg0 + 8) * 4 + 3]);

    float* outbase = g_att + ((size_t)b * SS + seg * SEGL + i0) * 1024 + h * 128;
#pragma unroll
    for (int tn = 0; tn < 4; tn++) {
        int col = wn * 32 + tn * 8 + 2 * tq;
        float be0 = __ldg(betas + h * 128 + col);
        float be1 = __ldg(betas + h * 128 + col + 1);
        float g0 = 1.0f / (1.0f + __expf(-be0));
        float g1 = 1.0f / (1.0f + __expf(-be1));
        float o0 = (1.0f - g0) * acc[tn][0] * invl_lo;
        float o1 = (1.0f - g1) * acc[tn][1] * invl_lo;
        float o2 = (1.0f - g0) * acc[tn][2] * invl_hi;
        float o3 = (1.0f - g1) * acc[tn][3] * invl_hi;
        *(float2*)(outbase + (size_t)rowg0 * 1024 + col) = make_float2(o0, o1);
        *(float2*)(outbase + (size_t)(rowg0 + 8) * 1024 + col) = make_float2(o2, o3);
    }
}

// -------------------- K7: mix — att += g * (sigma_q @ mem) / dn  (segs 1..7; RMW) --------------------
#define MIX_SMEM_FLOATS (64 * 132 + 128 * 132 + 64 + 128)
__global__ __launch_bounds__(256) void mix_kernel(const float* __restrict__ betas) {
    extern __shared__ float sm[];
    float* qs = sm;                 // 64x132 sigma_q (tf32)
    float* ms = qs + 64 * 132;      // 128x132 mem (tf32)
    float* dn = ms + 128 * 132;     // 64
    float* zs = dn + 64;            // 128

    int bh = blockIdx.x;
    int it = blockIdx.y;
    int seg = blockIdx.z + 1;       // 1..7
    int b = bh >> 3, h = bh & 7;
    int mat = bh * NSEG + seg;
    int i0 = it * 64;

    int t = threadIdx.x;
    int warp = t >> 5, lane = t & 31;
    int wm = warp >> 1, wn = warp & 1;
    int gid = lane >> 2, tq = lane & 3;
    int rowg0 = wm * 16 + gid;

    const float* qbase = g_q + ((size_t)b * SS + seg * SEGL) * 1024 + h * 128;
    const float* memp  = g_mems + (size_t)mat * DKk * DVv;

    if (t < 128) zs[t] = g_zall[mat * DKk + t];

    int lrow = t >> 5, lcol4 = (t & 31) * 4;
#pragma unroll
    for (int f = 0; f < 8; f++) {
        int row = lrow + f * 8;
        float4 qv = *(const float4*)(qbase + (size_t)(i0 + row) * 1024 + lcol4);
        qv = cvt4tf(qv);
        qv.x = ftf(elu1(qv.x));
        qv.y = ftf(elu1(qv.y));
        qv.z = ftf(elu1(qv.z));
        qv.w = ftf(elu1(qv.w));
        *(float4*)(qs + row * 132 + lcol4) = qv;
    }
#pragma unroll
    for (int f = 0; f < 16; f++) {
        int row = lrow + f * 8;
        float4 mv = *(const float4*)(memp + (size_t)row * 128 + lcol4);
        *(float4*)(ms + row * 132 + lcol4) = cvt4tf(mv);
    }
    __syncthreads();

    if (t < 64) {
        float d = 0.0f;
#pragma unroll 8
        for (int kc = 0; kc < 128; kc++) d += qs[t * 132 + kc] * zs[kc];
        dn[t] = d;
    }
    __syncthreads();

    const uint32_t* qsu = (const uint32_t*)qs;
    const uint32_t* msu = (const uint32_t*)ms;

    float accm[8][4];
#pragma unroll
    for (int i = 0; i < 8; i++)
#pragma unroll
        for (int q = 0; q < 4; q++) accm[i][q] = 0.0f;

#pragma unroll
    for (int kb = 0; kb < 16; kb++) {
        int kofs = kb * 8;
        uint32_t a0 = qsu[rowg0 * 132 + kofs + tq];
        uint32_t a1 = qsu[(rowg0 + 8) * 132 + kofs + tq];
        uint32_t a2 = qsu[rowg0 * 132 + kofs + tq + 4];
        uint32_t a3 = qsu[(rowg0 + 8) * 132 + kofs + tq + 4];
#pragma unroll
        for (int tn = 0; tn < 8; tn++) {
            int n = wn * 64 + tn * 8 + gid;
            uint32_t b0 = msu[(kofs + tq) * 132 + n];
            uint32_t b1 = msu[(kofs + tq + 4) * 132 + n];
            mma8(accm[tn], a0, a1, a2, a3, b0, b1);
        }
    }

    float invd_lo = 1.0f / dn[rowg0];
    float invd_hi = 1.0f / dn[rowg0 + 8];

    float* outbase = g_att + ((size_t)b * SS + seg * SEGL + i0) * 1024 + h * 128;
#pragma unroll
    for (int tn = 0; tn < 8; tn++) {
        int col = wn * 64 + tn * 8 + 2 * tq;
        float be0 = __ldg(betas + h * 128 + col);
        float be1 = __ldg(betas + h * 128 + col + 1);
        float g0 = 1.0f / (1.0f + __expf(-be0));
        float g1 = 1.0f / (1.0f + __expf(-be1));
        float2 lo = *(float2*)(outbase + (size_t)rowg0 * 1024 + col);
        float2 hi = *(float2*)(outbase + (size_t)(rowg0 + 8) * 1024 + col);
        lo.x += g0 * accm[tn][0] * invd_lo;
        lo.y += g1 * accm[tn][1] * invd_lo;
        hi.x += g0 * accm[tn][2] * invd_hi;
        hi.y += g1 * accm[tn][3] * invd_hi;
        *(float2*)(outbase + (size_t)rowg0 * 1024 + col) = lo;
        *(float2*)(outbase + (size_t)(rowg0 + 8) * 1024 + col) = hi;
    }
}

// -------------------- launch (fork-join; mix on side stream overlapped with out_seg0) --------------------
extern "C" void kernel_launch(void* const* d_in, const int* in_sizes, int n_in,
                              void* d_out, int out_size) {
    const float* x     = (const float*)d_in[0];
    const float* Wk    = (const float*)d_in[1];
    const float* Wv    = (const float*)d_in[2];
    const float* Wq    = (const float*)d_in[3];
    const float* Wout  = (const float*)d_in[4];
    const float* betas = (const float*)d_in[5];
    float* out = (float*)d_out;

    cudaFuncSetAttribute(recur_kernel, cudaFuncAttributeMaxDynamicSharedMemorySize,
                         RECUR_SMEM_FLOATS * (int)sizeof(float));
    cudaFuncSetAttribute(flashqkv_kernel, cudaFuncAttributeMaxDynamicSharedMemorySize,
                         FQKV_SMEM_FLOATS * (int)sizeof(float));
    cudaFuncSetAttribute(mix_kernel, cudaFuncAttributeMaxDynamicSharedMemorySize,
                         MIX_SMEM_FLOATS * (int)sizeof(float));

    cudaStream_t s2;
    cudaStreamCreate(&s2);
    cudaEvent_t e1, ef, e3;
    cudaEventCreateWithFlags(&e1, cudaEventDisableTiming);
    cudaEventCreateWithFlags(&ef, cudaEventDisableTiming);
    cudaEventCreateWithFlags(&e3, cudaEventDisableTiming);

    proj_mma<<<dim3(64, 8, 3), 256>>>(x, Wq, Wk, Wv);

    // fork: sigma_k pipeline on side stream
    cudaEventRecord(e1, 0);
    cudaStreamWaitEvent(s2, e1, 0);
    sig_kernel<<<dim3(BH, NSEG, 8), 256, 0, s2>>>();
    zprefix_kernel<<<BH, 128, 0, s2>>>();
    dn_kernel<<<dim3(MATS, 4), 128, 0, s2>>>();
    pd_kernel<<<dim3(MATS, 2), 256, 0, s2>>>();
    recur_kernel<<<dim3(BH, 4), 256, RECUR_SMEM_FLOATS * sizeof(float), s2>>>();

    // concurrently: causal attention (long pole) on main stream
    flashqkv_kernel<<<dim3(BH, 8, 8), 512, FQKV_SMEM_FLOATS * sizeof(float)>>>(betas);
    cudaEventRecord(ef, 0);

    // mix (needs chain results + flash's g_att) on side stream;
    // out over segment-0 rows (independent of mix) runs concurrently on main.
    cudaStreamWaitEvent(s2, ef, 0);
    mix_kernel<<<dim3(BH, 8, 7), 256, MIX_SMEM_FLOATS * sizeof(float), s2>>>(betas);
    cudaEventRecord(e3, s2);

    out_seg0_mma<<<dim3(8, 8), 256>>>(Wout, out);

    // join: remaining out tiles need mix's updates
    cudaStreamWaitEvent(0, e3, 0);
    out_rest_mma<<<dim3(56, 8), 256>>>(Wout, out);
}

// round 17
// speedup vs baseline: 1.0157x; 1.0095x over previous
#include <cuda_runtime.h>
#include <cstdint>

#define BB 2
#define SS 4096
#define DD 1024
#define HH 8
#define DKk 128
#define DVv 128
#define SEGL 512
#define NSEG 8
#define BH (BB*HH)
#define MATS (BH*NSEG)   // 128

#define SCALE 0.08838834764831845f  // 1/sqrt(128)

// -------------------- scratch --------------------
__device__ float g_q[(size_t)BB*SS*HH*DKk];
__device__ float g_k[(size_t)BB*SS*HH*DKk];
__device__ float g_v[(size_t)BB*SS*HH*DVv];
__device__ float g_att[(size_t)BB*SS*HH*DVv];
__device__ float g_skT[(size_t)MATS*DKk*SEGL];
__device__ float g_P1[(size_t)MATS*DKk*DVv];
__device__ float g_D [(size_t)MATS*DKk*DVv];
__device__ float g_mems[(size_t)MATS*DKk*DVv];
__device__ float g_zall[MATS*DKk];
__device__ float g_zsp[MATS*8*DKk];
__device__ float g_dnv[MATS*SEGL];

// -------------------- tf32 helpers --------------------
__device__ __forceinline__ uint32_t f2tf(float f) {
    uint32_t u; asm("cvt.rna.tf32.f32 %0, %1;" : "=r"(u) : "f"(f)); return u;
}
__device__ __forceinline__ float ftf(float f) { return __uint_as_float(f2tf(f)); }
__device__ __forceinline__ float4 cvt4tf(float4 v) {
    float4 r;
    r.x = ftf(v.x); r.y = ftf(v.y); r.z = ftf(v.z); r.w = ftf(v.w);
    return r;
}
__device__ __forceinline__ void mma8(float* c, uint32_t a0, uint32_t a1, uint32_t a2, uint32_t a3,
                                     uint32_t b0, uint32_t b1) {
    asm volatile("mma.sync.aligned.m16n8k8.row.col.f32.tf32.tf32.f32 "
                 "{%0,%1,%2,%3}, {%4,%5,%6,%7}, {%8,%9}, {%0,%1,%2,%3};"
                 : "+f"(c[0]), "+f"(c[1]), "+f"(c[2]), "+f"(c[3])
                 : "r"(a0), "r"(a1), "r"(a2), "r"(a3), "r"(b0), "r"(b1));
}
__device__ __forceinline__ float elu1(float x) { return (x > 0.0f) ? x + 1.0f : __expf(x); }

__device__ __forceinline__ void cpa16(uint32_t saddr, const float* gaddr) {
    asm volatile("cp.async.cg.shared.global [%0], [%1], 16;" :: "r"(saddr), "l"(gaddr));
}

// -------------------- cp.async 4-stage 128x128 CTA tf32 GEMM (proj/out) --------------------
// tf32 conversion at fragment load: values identical to store-side conversion.
template<int K>
__device__ __forceinline__ void gemm_body_ca(const float* __restrict__ A, int lda,
                                             const float* __restrict__ Bb, int ldb,
                                             float* __restrict__ C, int ldc,
                                             int n0, int m0) {
    __shared__ __align__(16) float As[4][128 * 20];
    __shared__ __align__(16) float Bs[4][16 * 136];

    int t = threadIdx.x;
    int ar = t >> 2, ac = (t & 3) * 4;
    int br = t >> 5, bc = (t & 31) * 4;
    int warp = t >> 5, lane = t & 31;
    int wm = warp >> 2, wn = warp & 3;
    int gid = lane >> 2, tq = lane & 3;

    const float* Ag0 = A + (size_t)(m0 + ar) * lda + ac;
    const float* Ag1 = Ag0 + (size_t)64 * lda;
    const float* Bg0 = Bb + (size_t)br * ldb + bc;
    const float* Bg1 = Bg0 + (size_t)8 * ldb;

    uint32_t as0 = (uint32_t)__cvta_generic_to_shared(&As[0][ar * 20 + ac]);
    uint32_t as1 = (uint32_t)__cvta_generic_to_shared(&As[0][(ar + 64) * 20 + ac]);
    uint32_t bs0 = (uint32_t)__cvta_generic_to_shared(&Bs[0][br * 136 + bc]);
    uint32_t bs1 = (uint32_t)__cvta_generic_to_shared(&Bs[0][(br + 8) * 136 + bc]);
    const uint32_t ASTR = 128 * 20 * 4;
    const uint32_t BSTR = 16 * 136 * 4;

    const int NST = K / 16;

    // prologue: stages 0..2 in flight
#pragma unroll
    for (int s = 0; s < 3; s++) {
        cpa16(as0 + s * ASTR, Ag0 + s * 16);
        cpa16(as1 + s * ASTR, Ag1 + s * 16);
        cpa16(bs0 + s * BSTR, Bg0 + (size_t)s * 16 * ldb);
        cpa16(bs1 + s * BSTR, Bg1 + (size_t)s * 16 * ldb);
        asm volatile("cp.async.commit_group;");
    }

    float acc[4][4][4];
#pragma unroll
    for (int i = 0; i < 4; i++)
#pragma unroll
        for (int j = 0; j < 4; j++)
#pragma unroll
            for (int q = 0; q < 4; q++) acc[i][j][q] = 0.0f;

    for (int ks = 0; ks < NST; ks++) {
        asm volatile("cp.async.wait_group 2;");
        __syncthreads();

        int buf = ks & 3;
        const float* Af = As[buf];
        const float* Bf = Bs[buf];
#pragma unroll
        for (int kb = 0; kb < 16; kb += 8) {
            uint32_t af[4][4], bf[4][2];
#pragma unroll
            for (int tm = 0; tm < 4; tm++) {
                int mb = wm * 64 + tm * 16;
                af[tm][0] = f2tf(Af[(mb + gid) * 20 + kb + tq]);
                af[tm][1] = f2tf(Af[(mb + gid + 8) * 20 + kb + tq]);
                af[tm][2] = f2tf(Af[(mb + gid) * 20 + kb + tq + 4]);
                af[tm][3] = f2tf(Af[(mb + gid + 8) * 20 + kb + tq + 4]);
            }
#pragma unroll
            for (int tn = 0; tn < 4; tn++) {
                int nb = wn * 32 + tn * 8 + gid;
                bf[tn][0] = f2tf(Bf[(kb + tq) * 136 + nb]);
                bf[tn][1] = f2tf(Bf[(kb + tq + 4) * 136 + nb]);
            }
#pragma unroll
            for (int tm = 0; tm < 4; tm++)
#pragma unroll
                for (int tn = 0; tn < 4; tn++)
                    mma8(acc[tm][tn], af[tm][0], af[tm][1], af[tm][2], af[tm][3],
                         bf[tn][0], bf[tn][1]);
        }

        int ns = ks + 3;
        if (ns < NST) {
            int nb2 = ns & 3;
            cpa16(as0 + nb2 * ASTR, Ag0 + ns * 16);
            cpa16(as1 + nb2 * ASTR, Ag1 + ns * 16);
            cpa16(bs0 + nb2 * BSTR, Bg0 + (size_t)ns * 16 * ldb);
            cpa16(bs1 + nb2 * BSTR, Bg1 + (size_t)ns * 16 * ldb);
        }
        asm volatile("cp.async.commit_group;");   // uniform group count (empty ok)
    }

#pragma unroll
    for (int tm = 0; tm < 4; tm++) {
        int row = m0 + wm * 64 + tm * 16 + gid;
#pragma unroll
        for (int tn = 0; tn < 4; tn++) {
            int col = n0 + wn * 32 + tn * 8 + 2 * tq;
            *(float2*)&C[(size_t)row * ldc + col] = make_float2(acc[tm][tn][0], acc[tm][tn][1]);
            *(float2*)&C[(size_t)(row + 8) * ldc + col] = make_float2(acc[tm][tn][2], acc[tm][tn][3]);
        }
    }
}

__global__ __launch_bounds__(256) void proj_mma(const float* __restrict__ x,
                                                const float* __restrict__ Wq,
                                                const float* __restrict__ Wk,
                                                const float* __restrict__ Wv) {
    const float* W = (blockIdx.z == 0) ? Wq : (blockIdx.z == 1) ? Wk : Wv;
    float* C = (blockIdx.z == 0) ? g_q : (blockIdx.z == 1) ? g_k : g_v;
    gemm_body_ca<1024>(x, 1024, W + (size_t)blockIdx.y * 131072, 128,
                       C, 1024, blockIdx.y * 128, blockIdx.x * 128);
}

// out over segment-0 rows only (m-tiles 0..3 and 32..35) — depends only on flash
__global__ __launch_bounds__(256) void out_seg0_mma(const float* __restrict__ Wout,
                                                    float* __restrict__ C) {
    int x = blockIdx.x;
    int mt = (x < 4) ? x : (x + 28);
    gemm_body_ca<1024>(g_att, 1024, Wout + (size_t)blockIdx.y * 128, 1024,
                       C, 1024, blockIdx.y * 128, mt * 128);
}

// out over the remaining 56 m-tiles — depends on mix
__global__ __launch_bounds__(256) void out_rest_mma(const float* __restrict__ Wout,
                                                    float* __restrict__ C) {
    int x = blockIdx.x;
    int mt = (x < 28) ? (x + 4) : (x + 8);
    gemm_body_ca<1024>(g_att, 1024, Wout + (size_t)blockIdx.y * 128, 1024,
                       C, 1024, blockIdx.y * 128, mt * 128);
}

// -------------------- K1: sigma_k + transpose + z partials --------------------
__global__ __launch_bounds__(256) void sig_kernel() {
    __shared__ float sm[64 * 132];
    int bh = blockIdx.x, seg = blockIdx.y, stile = blockIdx.z;
    int b = bh >> 3, h = bh & 7;
    int mat = bh * NSEG + seg;
    int s0 = stile * 64;
    int t = threadIdx.x;

    const float* kbase = g_k + ((size_t)b * SS + seg * SEGL + s0) * 1024 + h * 128;
#pragma unroll
    for (int p = 0; p < 32; p++) {
        int lin = t + p * 256;
        int row = lin >> 7, col = lin & 127;
        sm[row * 132 + col] = elu1(kbase[(size_t)row * 1024 + col]);
    }
    __syncthreads();

    float* skT = g_skT + (size_t)mat * DKk * SEGL;
#pragma unroll
    for (int p = 0; p < 32; p++) {
        int lin = t + p * 256;
        int kc = lin >> 6, scol = lin & 63;
        skT[(size_t)kc * SEGL + s0 + scol] = sm[scol * 132 + kc];
    }
    if (t < 128) {
        float zs = 0.0f;
#pragma unroll 8
        for (int s = 0; s < 64; s++) zs += sm[s * 132 + t];
        g_zsp[(mat * 8 + stile) * DKk + t] = zs;
    }
}

// -------------------- K2: z prefix --------------------
__global__ void zprefix_kernel() {
    int bh = blockIdx.x, t = threadIdx.x;  // block 128
    float z = 1.0f / (float)DKk;
    for (int s = 0; s < NSEG; s++) {
        int mat = bh * NSEG + s;
        g_zall[mat * DKk + t] = z;
#pragma unroll
        for (int st = 0; st < 8; st++) z += g_zsp[(mat * 8 + st) * DKk + t];
    }
}

// -------------------- K3: per-token 1/dn (grid split x4) --------------------
__global__ __launch_bounds__(128) void dn_kernel() {
    __shared__ float zs[128];
    int mat = blockIdx.x;
    int s0 = blockIdx.y * 128;
    int bh = mat >> 3, seg = mat & 7;
    int b = bh >> 3, h = bh & 7;
    int t = threadIdx.x;
    zs[t] = g_zall[mat * DKk + t];
    __syncthreads();
    const float* kr = g_k + ((size_t)b * SS + seg * SEGL + s0 + t) * 1024 + h * 128;
    float d = 0.0f;
#pragma unroll 8
    for (int i = 0; i < 32; i++) {
        float4 v = *(const float4*)(kr + i * 4);
        d += elu1(v.x) * zs[i * 4 + 0];
        d += elu1(v.y) * zs[i * 4 + 1];
        d += elu1(v.z) * zs[i * 4 + 2];
        d += elu1(v.w) * zs[i * 4 + 3];
    }
    g_dnv[mat * SEGL + s0 + t] = 1.0f / d;
}

// -------------------- K4: P1 and D GEMMs (old-style body; B has elu transform) --------------------
__global__ __launch_bounds__(256) void pd_kernel() {
    __shared__ float As[2][128 * 20];
    __shared__ float Bs[2][16 * 136];

    int mat = blockIdx.x;
    bool isD = (blockIdx.y == 1);
    int bh = mat >> 3, seg = mat & 7;
    int b = bh >> 3, h = bh & 7;

    const float* A = g_skT + (size_t)mat * DKk * SEGL;
    const float* Bb = (isD ? g_k : g_v) + ((size_t)b * SS + seg * SEGL) * 1024 + h * 128;
    float* C = (isD ? g_D : g_P1) + (size_t)mat * DKk * DVv;
    const float* invp = g_dnv + mat * SEGL;

    int t = threadIdx.x;
    int ar = t >> 2, ac = (t & 3) * 4;
    int br = t >> 5, bc = (t & 31) * 4;
    int warp = t >> 5, lane = t & 31;
    int wm = warp >> 2, wn = warp & 3;
    int gid = lane >> 2, tq = lane & 3;

    const float* Ap0 = A + (size_t)ar * SEGL + ac;
    const float* Ap1 = Ap0 + (size_t)64 * SEGL;
    const float* Bp0 = Bb + (size_t)br * 1024 + bc;
    const float* Bp1 = Bp0 + (size_t)8 * 1024;

    float4 a0r = *(const float4*)Ap0;
    float4 a1r = *(const float4*)Ap1;
    float4 b0r = *(const float4*)Bp0;
    float4 b1r = *(const float4*)Bp1;
    float iv0 = isD ? invp[br] : 1.0f;
    float iv1 = isD ? invp[8 + br] : 1.0f;

    float4 tb0 = b0r, tb1 = b1r;
    if (isD) {
        tb0 = make_float4(elu1(b0r.x) * iv0, elu1(b0r.y) * iv0, elu1(b0r.z) * iv0, elu1(b0r.w) * iv0);
        tb1 = make_float4(elu1(b1r.x) * iv1, elu1(b1r.y) * iv1, elu1(b1r.z) * iv1, elu1(b1r.w) * iv1);
    }
    *(float4*)(As[0] + ar * 20 + ac)        = cvt4tf(a0r);
    *(float4*)(As[0] + (ar + 64) * 20 + ac) = cvt4tf(a1r);
    *(float4*)(Bs[0] + br * 136 + bc)       = cvt4tf(tb0);
    *(float4*)(Bs[0] + (br + 8) * 136 + bc) = cvt4tf(tb1);
    __syncthreads();

    float acc[4][4][4];
#pragma unroll
    for (int i = 0; i < 4; i++)
#pragma unroll
        for (int j = 0; j < 4; j++)
#pragma unroll
            for (int q = 0; q < 4; q++) acc[i][j][q] = 0.0f;

    int cur = 0;
    for (int k0 = 0; k0 < SEGL; k0 += 16) {
        bool more = (k0 + 16 < SEGL);
        if (more) {
            Ap0 += 16; Ap1 += 16;
            Bp0 += (size_t)16 * 1024; Bp1 += (size_t)16 * 1024;
            a0r = *(const float4*)Ap0; a1r = *(const float4*)Ap1;
            b0r = *(const float4*)Bp0; b1r = *(const float4*)Bp1;
            if (isD) { iv0 = invp[k0 + 16 + br]; iv1 = invp[k0 + 24 + br]; }
        }

        const uint32_t* Asu = (const uint32_t*)As[cur];
        const uint32_t* Bsu = (const uint32_t*)Bs[cur];
#pragma unroll
        for (int kb = 0; kb < 16; kb += 8) {
            uint32_t af[4][4], bf[4][2];
#pragma unroll
            for (int tm = 0; tm < 4; tm++) {
                int mb = wm * 64 + tm * 16;
                af[tm][0] = Asu[(mb + gid) * 20 + kb + tq];
                af[tm][1] = Asu[(mb + gid + 8) * 20 + kb + tq];
                af[tm][2] = Asu[(mb + gid) * 20 + kb + tq + 4];
                af[tm][3] = Asu[(mb + gid + 8) * 20 + kb + tq + 4];
            }
#pragma unroll
            for (int tn = 0; tn < 4; tn++) {
                int nb = wn * 32 + tn * 8 + gid;
                bf[tn][0] = Bsu[(kb + tq) * 136 + nb];
                bf[tn][1] = Bsu[(kb + tq + 4) * 136 + nb];
            }
#pragma unroll
            for (int tm = 0; tm < 4; tm++)
#pragma unroll
                for (int tn = 0; tn < 4; tn++)
                    mma8(acc[tm][tn], af[tm][0], af[tm][1], af[tm][2], af[tm][3],
                         bf[tn][0], bf[tn][1]);
        }

        if (more) {
            float4 nb0 = b0r, nb1 = b1r;
            if (isD) {
                nb0 = make_float4(elu1(b0r.x) * iv0, elu1(b0r.y) * iv0, elu1(b0r.z) * iv0, elu1(b0r.w) * iv0);
                nb1 = make_float4(elu1(b1r.x) * iv1, elu1(b1r.y) * iv1, elu1(b1r.z) * iv1, elu1(b1r.w) * iv1);
            }
            int nxt = cur ^ 1;
            *(float4*)(As[nxt] + ar * 20 + ac)        = cvt4tf(a0r);
            *(float4*)(As[nxt] + (ar + 64) * 20 + ac) = cvt4tf(a1r);
            *(float4*)(Bs[nxt] + br * 136 + bc)       = cvt4tf(nb0);
            *(float4*)(Bs[nxt] + (br + 8) * 136 + bc) = cvt4tf(nb1);
        }
        __syncthreads();
        cur ^= 1;
    }

#pragma unroll
    for (int tm = 0; tm < 4; tm++) {
        int row = wm * 64 + tm * 16 + gid;
#pragma unroll
        for (int tn = 0; tn < 4; tn++) {
            int col = wn * 32 + tn * 8 + 2 * tq;
            *(float2*)&C[(size_t)row * 128 + col] = make_float2(acc[tm][tn][0], acc[tm][tn][1]);
            *(float2*)&C[(size_t)(row + 8) * 128 + col] = make_float2(acc[tm][tn][2], acc[tm][tn][3]);
        }
    }
}

// -------------------- K5: recurrence, split 4x along mem columns --------------------
#define RECUR_SMEM_FLOATS (128 * 132 + 128 * 36)
__global__ __launch_bounds__(256) void recur_kernel() {
    extern __shared__ float sm[];
    float* db  = sm;               // [128][132] D staging
    float* mem = sm + 128 * 132;   // [128][36] column slab

    int bh = blockIdx.x;
    int c0 = blockIdx.y * 32;
    int t = threadIdx.x;
    int warp = t >> 5, lane = t & 31;
    int gid = lane >> 2, tq = lane & 3;
    int rowg = warp * 16 + gid;

#pragma unroll
    for (int p = 0; p < 18; p++) {
        int lin = t + p * 256;
        if (lin < 128 * 36) mem[lin] = 0.0f;
    }
    __syncthreads();

    for (int s = 0; s < NSEG; s++) {
        int mat = bh * NSEG + s;
        float* snap = g_mems + (size_t)mat * DKk * DVv;
#pragma unroll
        for (int p = 0; p < 16; p++) {
            int lin = t + p * 256;
            int row = lin >> 5, col = lin & 31;
            snap[(size_t)row * DVv + c0 + col] = mem[row * 36 + col];
        }
        if (s == NSEG - 1) break;

        const float* Dp = g_D + (size_t)mat * DKk * DVv;
#pragma unroll
        for (int p = 0; p < 64; p++) {
            int lin = t + p * 256;
            int row = lin >> 7, col = lin & 127;
            db[row * 132 + col] = Dp[lin];
        }
        __syncthreads();

        const float* P1p = g_P1 + (size_t)mat * DKk * DVv;
        float acc[4][4];
#pragma unroll
        for (int tn = 0; tn < 4; tn++) {
            int col = c0 + tn * 8 + 2 * tq;
            float2 c01 = *(const float2*)&P1p[(size_t)rowg * DVv + col];
            float2 c23 = *(const float2*)&P1p[(size_t)(rowg + 8) * DVv + col];
            acc[tn][0] = c01.x; acc[tn][1] = c01.y;
            acc[tn][2] = c23.x; acc[tn][3] = c23.y;
        }

#pragma unroll
        for (int kb = 0; kb < 16; kb++) {
            int kofs = kb * 8;
            uint32_t a0 = f2tf(-db[rowg * 132 + kofs + tq]);
            uint32_t a1 = f2tf(-db[(rowg + 8) * 132 + kofs + tq]);
            uint32_t a2 = f2tf(-db[rowg * 132 + kofs + tq + 4]);
            uint32_t a3 = f2tf(-db[(rowg + 8) * 132 + kofs + tq + 4]);
#pragma unroll
            for (int tn = 0; tn < 4; tn++) {
                int n = tn * 8 + gid;
                uint32_t b0 = f2tf(mem[(kofs + tq) * 36 + n]);
                uint32_t b1 = f2tf(mem[(kofs + tq + 4) * 36 + n]);
                mma8(acc[tn], a0, a1, a2, a3, b0, b1);
            }
        }
        __syncthreads();

#pragma unroll
        for (int tn = 0; tn < 4; tn++) {
            int col = tn * 8 + 2 * tq;
            mem[rowg * 36 + col]           += acc[tn][0];
            mem[rowg * 36 + col + 1]       += acc[tn][1];
            mem[(rowg + 8) * 36 + col]     += acc[tn][2];
            mem[(rowg + 8) * 36 + col + 1] += acc[tn][3];
        }
        __syncthreads();
    }
}

// -------------------- K6: causal flash attention (512 threads, i-tile 64) --------------------
#define FQKV_SMEM_FLOATS (3 * 64 * 132 + 64 * 68 + 64 * 4)
__global__ __launch_bounds__(512) void flashqkv_kernel(const float* __restrict__ betas) {
    extern __shared__ float sm[];
    float* qs = sm;
    float* ks = qs + 64 * 132;
    float* vs = ks + 64 * 132;
    float* ps = vs + 64 * 132;
    float* l4 = ps + 64 * 68;

    int bh = blockIdx.x;
    int it = 7 - blockIdx.y;
    int seg = blockIdx.z;
    int b = bh >> 3, h = bh & 7;
    int i0 = it * 64;

    int t = threadIdx.x;
    int warp = t >> 5, lane = t & 31;
    int wm = warp >> 2, wn = warp & 3;
    int gid = lane >> 2, tq = lane & 3;
    int rowg0 = wm * 16 + gid;

    const float* qbase = g_q + ((size_t)b * SS + seg * SEGL) * 1024 + h * 128;
    const float* kbase = g_k + ((size_t)b * SS + seg * SEGL) * 1024 + h * 128;
    const float* vbase = g_v + ((size_t)b * SS + seg * SEGL) * 1024 + h * 128;

    int lrow = t >> 5, lcol4 = (t & 31) * 4;

#pragma unroll
    for (int f = 0; f < 4; f++) {
        int row = lrow + f * 16;
        float4 qv = *(const float4*)(qbase + (size_t)(i0 + row) * 1024 + lcol4);
        *(float4*)(qs + row * 132 + lcol4) = cvt4tf(qv);
    }

    float acc[4][4];
#pragma unroll
    for (int i = 0; i < 4; i++)
#pragma unroll
        for (int q = 0; q < 4; q++) acc[i][q] = 0.0f;
    float plo = 0.0f, phi = 0.0f;

    const uint32_t* qsu = (const uint32_t*)qs;
    const uint32_t* ksu = (const uint32_t*)ks;
    const uint32_t* vsu = (const uint32_t*)vs;
    const uint32_t* psu = (const uint32_t*)ps;

    float4 kreg[4], vreg[4];
#pragma unroll
    for (int f = 0; f < 4; f++) {
        int row = lrow + f * 16;
        kreg[f] = *(const float4*)(kbase + (size_t)row * 1024 + lcol4);
        vreg[f] = *(const float4*)(vbase + (size_t)row * 1024 + lcol4);
    }

    for (int jt = 0; jt <= it; jt++) {
        __syncthreads();
#pragma unroll
        for (int f = 0; f < 4; f++) {
            int row = lrow + f * 16;
            *(float4*)(ks + row * 132 + lcol4) = cvt4tf(kreg[f]);
            *(float4*)(vs + row * 132 + lcol4) = cvt4tf(vreg[f]);
        }
        __syncthreads();

        if (jt < it) {
            int j0n = (jt + 1) * 64;
#pragma unroll
            for (int f = 0; f < 4; f++) {
                int row = j0n + lrow + f * 16;
                kreg[f] = *(const float4*)(kbase + (size_t)row * 1024 + lcol4);
                vreg[f] = *(const float4*)(vbase + (size_t)row * 1024 + lcol4);
            }
        }

        int j0 = jt * 64;
        float sc[2][4];
#pragma unroll
        for (int tn = 0; tn < 2; tn++)
#pragma unroll
            for (int q = 0; q < 4; q++) sc[tn][q] = 0.0f;

#pragma unroll
        for (int kb = 0; kb < 16; kb++) {
            int kofs = kb * 8;
            uint32_t a0 = qsu[rowg0 * 132 + kofs + tq];
            uint32_t a1 = qsu[(rowg0 + 8) * 132 + kofs + tq];
            uint32_t a2 = qsu[rowg0 * 132 + kofs + tq + 4];
            uint32_t a3 = qsu[(rowg0 + 8) * 132 + kofs + tq + 4];
#pragma unroll
            for (int tn = 0; tn < 2; tn++) {
                int n = wn * 16 + tn * 8 + gid;
                uint32_t b0 = ksu[n * 132 + kofs + tq];
                uint32_t b1 = ksu[n * 132 + kofs + tq + 4];
                mma8(sc[tn], a0, a1, a2, a3, b0, b1);
            }
        }

#pragma unroll
        for (int tn = 0; tn < 2; tn++) {
            int ncol = wn * 16 + tn * 8 + 2 * tq;
            int jg0 = j0 + ncol, jg1 = j0 + ncol + 1;
            int ig_lo = i0 + rowg0, ig_hi = i0 + rowg0 + 8;
            float p0 = (jg0 <= ig_lo) ? __expf(sc[tn][0] * SCALE) : 0.0f;
            float p1 = (jg1 <= ig_lo) ? __expf(sc[tn][1] * SCALE) : 0.0f;
            float p2 = (jg0 <= ig_hi) ? __expf(sc[tn][2] * SCALE) : 0.0f;
            float p3 = (jg1 <= ig_hi) ? __expf(sc[tn][3] * SCALE) : 0.0f;
            plo += p0 + p1;
            phi += p2 + p3;
            *(float2*)(ps + rowg0 * 68 + ncol) = make_float2(ftf(p0), ftf(p1));
            *(float2*)(ps + (rowg0 + 8) * 68 + ncol) = make_float2(ftf(p2), ftf(p3));
        }
        __syncthreads();

#pragma unroll
        for (int kb = 0; kb < 8; kb++) {
            int kofs = kb * 8;
            uint32_t a0 = psu[rowg0 * 68 + kofs + tq];
            uint32_t a1 = psu[(rowg0 + 8) * 68 + kofs + tq];
            uint32_t a2 = psu[rowg0 * 68 + kofs + tq + 4];
            uint32_t a3 = psu[(rowg0 + 8) * 68 + kofs + tq + 4];
#pragma unroll
            for (int tn = 0; tn < 4; tn++) {
                int n = wn * 32 + tn * 8 + gid;
                uint32_t b0 = vsu[(kofs + tq) * 132 + n];
                uint32_t b1 = vsu[(kofs + tq + 4) * 132 + n];
                mma8(acc[tn], a0, a1, a2, a3, b0, b1);
            }
        }
    }

    plo += __shfl_xor_sync(0xffffffffu, plo, 1);
    plo += __shfl_xor_sync(0xffffffffu, plo, 2);
    phi += __shfl_xor_sync(0xffffffffu, phi, 1);
    phi += __shfl_xor_sync(0xffffffffu, phi, 2);
    if (tq == 0) {
        l4[rowg0 * 4 + wn] = plo;
        l4[(rowg0 + 8) * 4 + wn] = phi;
    }
    __syncthreads();

    float invl_lo = 1.0f / (l4[rowg0 * 4] + l4[rowg0 * 4 + 1] + l4[rowg0 * 4 + 2] + l4[rowg0 * 4 + 3]);
    float invl_hi = 1.0f / (l4[(rowg0 + 8) * 4] + l4[(rowg0 + 8) * 4 + 1] + l4[(rowg0 + 8) * 4 + 2] + l4[(rowg0 + 8) * 4 + 3]);

    float* outbase = g_att + ((size_t)b * SS + seg * SEGL + i0) * 1024 + h * 128;
#pragma unroll
    for (int tn = 0; tn < 4; tn++) {
        int col = wn * 32 + tn * 8 + 2 * tq;
        float be0 = __ldg(betas + h * 128 + col);
        float be1 = __ldg(betas + h * 128 + col + 1);
        float g0 = 1.0f / (1.0f + __expf(-be0));
        float g1 = 1.0f / (1.0f + __expf(-be1));
        float o0 = (1.0f - g0) * acc[tn][0] * invl_lo;
        float o1 = (1.0f - g1) * acc[tn][1] * invl_lo;
        float o2 = (1.0f - g0) * acc[tn][2] * invl_hi;
        float o3 = (1.0f - g1) * acc[tn][3] * invl_hi;
        *(float2*)(outbase + (size_t)rowg0 * 1024 + col) = make_float2(o0, o1);
        *(float2*)(outbase + (size_t)(rowg0 + 8) * 1024 + col) = make_float2(o2, o3);
    }
}

// -------------------- K7: mix — att += g * (sigma_q @ mem) / dn  (segs 1..7; RMW) --------------------
#define MIX_SMEM_FLOATS (64 * 132 + 128 * 132 + 64 + 128)
__global__ __launch_bounds__(256) void mix_kernel(const float* __restrict__ betas) {
    extern __shared__ float sm[];
    float* qs = sm;
    float* ms = qs + 64 * 132;
    float* dn = ms + 128 * 132;
    float* zs = dn + 64;

    int bh = blockIdx.x;
    int it = blockIdx.y;
    int seg = blockIdx.z + 1;
    int b = bh >> 3, h = bh & 7;
    int mat = bh * NSEG + seg;
    int i0 = it * 64;

    int t = threadIdx.x;
    int warp = t >> 5, lane = t & 31;
    int wm = warp >> 1, wn = warp & 1;
    int gid = lane >> 2, tq = lane & 3;
    int rowg0 = wm * 16 + gid;

    const float* qbase = g_q + ((size_t)b * SS + seg * SEGL) * 1024 + h * 128;
    const float* memp  = g_mems + (size_t)mat * DKk * DVv;

    if (t < 128) zs[t] = g_zall[mat * DKk + t];

    int lrow = t >> 5, lcol4 = (t & 31) * 4;
#pragma unroll
    for (int f = 0; f < 8; f++) {
        int row = lrow + f * 8;
        float4 qv = *(const float4*)(qbase + (size_t)(i0 + row) * 1024 + lcol4);
        qv = cvt4tf(qv);
        qv.x = ftf(elu1(qv.x));
        qv.y = ftf(elu1(qv.y));
        qv.z = ftf(elu1(qv.z));
        qv.w = ftf(elu1(qv.w));
        *(float4*)(qs + row * 132 + lcol4) = qv;
    }
#pragma unroll
    for (int f = 0; f < 16; f++) {
        int row = lrow + f * 8;
        float4 mv = *(const float4*)(memp + (size_t)row * 128 + lcol4);
        *(float4*)(ms + row * 132 + lcol4) = cvt4tf(mv);
    }
    __syncthreads();

    if (t < 64) {
        float d = 0.0f;
#pragma unroll 8
        for (int kc = 0; kc < 128; kc++) d += qs[t * 132 + kc] * zs[kc];
        dn[t] = d;
    }
    __syncthreads();

    const uint32_t* qsu = (const uint32_t*)qs;
    const uint32_t* msu = (const uint32_t*)ms;

    float accm[8][4];
#pragma unroll
    for (int i = 0; i < 8; i++)
#pragma unroll
        for (int q = 0; q < 4; q++) accm[i][q] = 0.0f;

#pragma unroll
    for (int kb = 0; kb < 16; kb++) {
        int kofs = kb * 8;
        uint32_t a0 = qsu[rowg0 * 132 + kofs + tq];
        uint32_t a1 = qsu[(rowg0 + 8) * 132 + kofs + tq];
        uint32_t a2 = qsu[rowg0 * 132 + kofs + tq + 4];
        uint32_t a3 = qsu[(rowg0 + 8) * 132 + kofs + tq + 4];
#pragma unroll
        for (int tn = 0; tn < 8; tn++) {
            int n = wn * 64 + tn * 8 + gid;
            uint32_t b0 = msu[(kofs + tq) * 132 + n];
            uint32_t b1 = msu[(kofs + tq + 4) * 132 + n];
            mma8(accm[tn], a0, a1, a2, a3, b0, b1);
        }
    }

    float invd_lo = 1.0f / dn[rowg0];
    float invd_hi = 1.0f / dn[rowg0 + 8];

    float* outbase = g_att + ((size_t)b * SS + seg * SEGL + i0) * 1024 + h * 128;
#pragma unroll
    for (int tn = 0; tn < 8; tn++) {
        int col = wn * 64 + tn * 8 + 2 * tq;
        float be0 = __ldg(betas + h * 128 + col);
        float be1 = __ldg(betas + h * 128 + col + 1);
        float g0 = 1.0f / (1.0f + __expf(-be0));
        float g1 = 1.0f / (1.0f + __expf(-be1));
        float2 lo = *(float2*)(outbase + (size_t)rowg0 * 1024 + col);
        float2 hi = *(float2*)(outbase + (size_t)(rowg0 + 8) * 1024 + col);
        lo.x += g0 * accm[tn][0] * invd_lo;
        lo.y += g1 * accm[tn][1] * invd_lo;
        hi.x += g0 * accm[tn][2] * invd_hi;
        hi.y += g1 * accm[tn][3] * invd_hi;
        *(float2*)(outbase + (size_t)rowg0 * 1024 + col) = lo;
        *(float2*)(outbase + (size_t)(rowg0 + 8) * 1024 + col) = hi;
    }
}

// -------------------- launch (fork-join; mix on side stream overlapped with out_seg0) --------------------
extern "C" void kernel_launch(void* const* d_in, const int* in_sizes, int n_in,
                              void* d_out, int out_size) {
    const float* x     = (const float*)d_in[0];
    const float* Wk    = (const float*)d_in[1];
    const float* Wv    = (const float*)d_in[2];
    const float* Wq    = (const float*)d_in[3];
    const float* Wout  = (const float*)d_in[4];
    const float* betas = (const float*)d_in[5];
    float* out = (float*)d_out;

    cudaFuncSetAttribute(recur_kernel, cudaFuncAttributeMaxDynamicSharedMemorySize,
                         RECUR_SMEM_FLOATS * (int)sizeof(float));
    cudaFuncSetAttribute(flashqkv_kernel, cudaFuncAttributeMaxDynamicSharedMemorySize,
                         FQKV_SMEM_FLOATS * (int)sizeof(float));
    cudaFuncSetAttribute(mix_kernel, cudaFuncAttributeMaxDynamicSharedMemorySize,
                         MIX_SMEM_FLOATS * (int)sizeof(float));

    cudaStream_t s2;
    cudaStreamCreate(&s2);
    cudaEvent_t e1, ef, e3;
    cudaEventCreateWithFlags(&e1, cudaEventDisableTiming);
    cudaEventCreateWithFlags(&ef, cudaEventDisableTiming);
    cudaEventCreateWithFlags(&e3, cudaEventDisableTiming);

    proj_mma<<<dim3(64, 8, 3), 256>>>(x, Wq, Wk, Wv);

    // fork: sigma_k pipeline on side stream
    cudaEventRecord(e1, 0);
    cudaStreamWaitEvent(s2, e1, 0);
    sig_kernel<<<dim3(BH, NSEG, 8), 256, 0, s2>>>();
    zprefix_kernel<<<BH, 128, 0, s2>>>();
    dn_kernel<<<dim3(MATS, 4), 128, 0, s2>>>();
    pd_kernel<<<dim3(MATS, 2), 256, 0, s2>>>();
    recur_kernel<<<dim3(BH, 4), 256, RECUR_SMEM_FLOATS * sizeof(float), s2>>>();

    // concurrently: causal attention (long pole) on main stream
    flashqkv_kernel<<<dim3(BH, 8, 8), 512, FQKV_SMEM_FLOATS * sizeof(float)>>>(betas);
    cudaEventRecord(ef, 0);

    // mix on side stream; out over segment-0 rows concurrently on main
    cudaStreamWaitEvent(s2, ef, 0);
    mix_kernel<<<dim3(BH, 8, 7), 256, MIX_SMEM_FLOATS * sizeof(float), s2>>>(betas);
    cudaEventRecord(e3, s2);

    out_seg0_mma<<<dim3(8, 8), 256>>>(Wout, out);

    // join: remaining out tiles need mix's updates
    cudaStreamWaitEvent(0, e3, 0);
    out_rest_mma<<<dim3(56, 8), 256>>>(Wout, out);
}